// round 11
// baseline (speedup 1.0000x reference)
#include <cuda_runtime.h>
#include <cuda_fp16.h>

#define NN   50000
#define EE   800000
#define INC  32
#define HIDC 64
#define MAXDEG 96

// -------------------- device scratch (no allocation allowed) ----------------
// Invariant: g_cnt is ZERO at entry of every kernel_launch call
// (zeroed at module load; restored by k_agg2 each call).
__device__ __align__(16) int    g_cnt[NN];            // degree + fill cursor
__device__ __align__(16) int    g_csrp[NN * MAXDEG];  // padded CSR: src by dst
__device__ __align__(16) float  g_agg1[NN * INC];     // normalized mean of x
__device__ __align__(16) __half g_agg2h[NN * HIDC];   // normalized mean of h (fp16)
__device__ __align__(16) __half g_h[NN * HIDC];       // layer-1 output (fp16)

// -------------------- f32x2 packed math helpers -----------------------------
__device__ __forceinline__ unsigned long long pack2(float lo, float hi) {
    unsigned long long r;
    asm("mov.b64 %0, {%1, %2};" : "=l"(r) : "f"(lo), "f"(hi));
    return r;
}
__device__ __forceinline__ void unpack2(float& lo, float& hi, unsigned long long v) {
    asm("mov.b64 {%0, %1}, %2;" : "=f"(lo), "=f"(hi) : "l"(v));
}
#define FMA2(d, a, b) asm("fma.rn.f32x2 %0, %1, %2, %0;" : "+l"(d) : "l"(a), "l"(b))

// ============================================================================
// Padded-CSR fill: 8 edges per thread (2x int4 loads, 8 independent chains)
// ============================================================================
__global__ __launch_bounds__(256)
void k_fill(const int* __restrict__ src, const int* __restrict__ dst) {
    int q = blockIdx.x * blockDim.x + threadIdx.x;   // octet id
    if (q >= EE / 8) return;
    int4 sA = __ldg((const int4*)src + 2 * q);
    int4 sB = __ldg((const int4*)src + 2 * q + 1);
    int4 dA = __ldg((const int4*)dst + 2 * q);
    int4 dB = __ldg((const int4*)dst + 2 * q + 1);
    int sl0 = atomicAdd(&g_cnt[dA.x], 1);
    int sl1 = atomicAdd(&g_cnt[dA.y], 1);
    int sl2 = atomicAdd(&g_cnt[dA.z], 1);
    int sl3 = atomicAdd(&g_cnt[dA.w], 1);
    int sl4 = atomicAdd(&g_cnt[dB.x], 1);
    int sl5 = atomicAdd(&g_cnt[dB.y], 1);
    int sl6 = atomicAdd(&g_cnt[dB.z], 1);
    int sl7 = atomicAdd(&g_cnt[dB.w], 1);
    if (sl0 < MAXDEG) g_csrp[dA.x * MAXDEG + sl0] = sA.x;
    if (sl1 < MAXDEG) g_csrp[dA.y * MAXDEG + sl1] = sA.y;
    if (sl2 < MAXDEG) g_csrp[dA.z * MAXDEG + sl2] = sA.z;
    if (sl3 < MAXDEG) g_csrp[dA.w * MAXDEG + sl3] = sA.w;
    if (sl4 < MAXDEG) g_csrp[dB.x * MAXDEG + sl4] = sB.x;
    if (sl5 < MAXDEG) g_csrp[dB.y * MAXDEG + sl5] = sB.y;
    if (sl6 < MAXDEG) g_csrp[dB.z * MAXDEG + sl6] = sB.z;
    if (sl7 < MAXDEG) g_csrp[dB.w * MAXDEG + sl7] = sB.w;
}

// ============================================================================
// Agg 1: 4 nodes per warp; 8 lanes x float4 cover the 32 channels.
// ============================================================================
__global__ __launch_bounds__(256)
void k_agg1(const float* __restrict__ x) {
    int gt   = blockIdx.x * blockDim.x + threadIdx.x;
    int wid  = gt >> 5;
    int lane = gt & 31;
    int sub  = lane >> 3;        // node within warp (0..3)
    int c4   = lane & 7;         // float4 channel group (0..7)
    int n = wid * 4 + sub;
    if (n >= NN) return;

    int deg  = g_cnt[n];
    int degc = deg < MAXDEG ? deg : MAXDEG;
    const int*    row = &g_csrp[n * MAXDEG];
    const float4* xp  = (const float4*)x;

    float4 acc = make_float4(0.f, 0.f, 0.f, 0.f);
    int j = 0;
    for (; j + 3 < degc; j += 4) {
        int4 s = __ldg((const int4*)(row + j));
        float4 v0 = __ldg(xp + (s.x * 8 + c4));
        float4 v1 = __ldg(xp + (s.y * 8 + c4));
        float4 v2 = __ldg(xp + (s.z * 8 + c4));
        float4 v3 = __ldg(xp + (s.w * 8 + c4));
        acc.x += (v0.x + v1.x) + (v2.x + v3.x);
        acc.y += (v0.y + v1.y) + (v2.y + v3.y);
        acc.z += (v0.z + v1.z) + (v2.z + v3.z);
        acc.w += (v0.w + v1.w) + (v2.w + v3.w);
    }
    for (; j < degc; j++) {
        float4 v = __ldg(xp + (__ldg(row + j) * 8 + c4));
        acc.x += v.x; acc.y += v.y; acc.z += v.z; acc.w += v.w;
    }
    float dinv = 1.0f / fmaxf((float)deg, 1.0f);
    acc.x *= dinv; acc.y *= dinv; acc.z *= dinv; acc.w *= dinv;
    ((float4*)g_agg1)[n * 8 + c4] = acc;
}

// ============================================================================
// Agg 2: 4 nodes per warp; 8 lanes x uint4 (8 fp16) cover the 64 channels.
// fp16 output. Also restores g_cnt[n] = 0 (last reader of deg).
// ============================================================================
__global__ __launch_bounds__(256)
void k_agg2() {
    int gt   = blockIdx.x * blockDim.x + threadIdx.x;
    int wid  = gt >> 5;
    int lane = gt & 31;
    int sub  = lane >> 3;        // node within warp (0..3)
    int c8   = lane & 7;         // 8-halves group (0..7)
    int n = wid * 4 + sub;
    if (n >= NN) return;

    int deg  = g_cnt[n];
    int degc = deg < MAXDEG ? deg : MAXDEG;
    const int*   row = &g_csrp[n * MAXDEG];
    const uint4* hp  = (const uint4*)g_h;    // 8 halves per uint4

    float acc[8];
#pragma unroll
    for (int i = 0; i < 8; i++) acc[i] = 0.f;

    int j = 0;
    for (; j + 7 < degc; j += 8) {
        int4 sA = __ldg((const int4*)(row + j));
        int4 sB = __ldg((const int4*)(row + j + 4));
        uint4 u0 = __ldg(hp + (sA.x * 8 + c8));
        uint4 u1 = __ldg(hp + (sA.y * 8 + c8));
        uint4 u2 = __ldg(hp + (sA.z * 8 + c8));
        uint4 u3 = __ldg(hp + (sA.w * 8 + c8));
        uint4 u4 = __ldg(hp + (sB.x * 8 + c8));
        uint4 u5 = __ldg(hp + (sB.y * 8 + c8));
        uint4 u6 = __ldg(hp + (sB.z * 8 + c8));
        uint4 u7 = __ldg(hp + (sB.w * 8 + c8));
#pragma unroll
        for (int q = 0; q < 8; q++) {
            uint4 u = (q == 0) ? u0 : (q == 1) ? u1 : (q == 2) ? u2 :
                      (q == 3) ? u3 : (q == 4) ? u4 : (q == 5) ? u5 :
                      (q == 6) ? u6 : u7;
            float2 f0 = __half22float2(*(__half2*)&u.x);
            float2 f1 = __half22float2(*(__half2*)&u.y);
            float2 f2 = __half22float2(*(__half2*)&u.z);
            float2 f3 = __half22float2(*(__half2*)&u.w);
            acc[0] += f0.x; acc[1] += f0.y;
            acc[2] += f1.x; acc[3] += f1.y;
            acc[4] += f2.x; acc[5] += f2.y;
            acc[6] += f3.x; acc[7] += f3.y;
        }
    }
    for (; j + 3 < degc; j += 4) {
        int4 s = __ldg((const int4*)(row + j));
        uint4 u0 = __ldg(hp + (s.x * 8 + c8));
        uint4 u1 = __ldg(hp + (s.y * 8 + c8));
        uint4 u2 = __ldg(hp + (s.z * 8 + c8));
        uint4 u3 = __ldg(hp + (s.w * 8 + c8));
#pragma unroll
        for (int q = 0; q < 4; q++) {
            uint4 u = (q == 0) ? u0 : (q == 1) ? u1 : (q == 2) ? u2 : u3;
            float2 f0 = __half22float2(*(__half2*)&u.x);
            float2 f1 = __half22float2(*(__half2*)&u.y);
            float2 f2 = __half22float2(*(__half2*)&u.z);
            float2 f3 = __half22float2(*(__half2*)&u.w);
            acc[0] += f0.x; acc[1] += f0.y;
            acc[2] += f1.x; acc[3] += f1.y;
            acc[4] += f2.x; acc[5] += f2.y;
            acc[6] += f3.x; acc[7] += f3.y;
        }
    }
    for (; j < degc; j++) {
        uint4 u = __ldg(hp + (__ldg(row + j) * 8 + c8));
        float2 f0 = __half22float2(*(__half2*)&u.x);
        float2 f1 = __half22float2(*(__half2*)&u.y);
        float2 f2 = __half22float2(*(__half2*)&u.z);
        float2 f3 = __half22float2(*(__half2*)&u.w);
        acc[0] += f0.x; acc[1] += f0.y;
        acc[2] += f1.x; acc[3] += f1.y;
        acc[4] += f2.x; acc[5] += f2.y;
        acc[6] += f3.x; acc[7] += f3.y;
    }
    float dinv = 1.0f / fmaxf((float)deg, 1.0f);
    __half2 p0 = __floats2half2_rn(acc[0]*dinv, acc[1]*dinv);
    __half2 p1 = __floats2half2_rn(acc[2]*dinv, acc[3]*dinv);
    __half2 p2 = __floats2half2_rn(acc[4]*dinv, acc[5]*dinv);
    __half2 p3 = __floats2half2_rn(acc[6]*dinv, acc[7]*dinv);
    uint4 pkt;
    pkt.x = *(unsigned int*)&p0;
    pkt.y = *(unsigned int*)&p1;
    pkt.z = *(unsigned int*)&p2;
    pkt.w = *(unsigned int*)&p3;
    ((uint4*)g_agg2h)[n * 8 + c8] = pkt;
    if (c8 == 0) g_cnt[n] = 0;   // restore invariant
}

// ============================================================================
// Layer 1 GEMM: h[n][o] = relu(a1[o]*([agg1 | x] @ [W1l;W1r])[n][o] + b1[o])
// 128 nodes x 64 outs, 256 threads, 4x8 tile; activations via LDS.128 over k.
// PAD=68 (stride 272B: 16B-aligned rows). Output stored fp16.
// ============================================================================
#define L1_PAD   68
#define L1_SIN   0
#define L1_SW    (128 * L1_PAD * 4)          // 34816
#define L1_ALPHA (L1_SW + 64 * 64 * 4)       // +16384
#define L1_BETA  (L1_ALPHA + 256)
#define L1_SMEM  (L1_BETA + 256)             // 51712

__global__ __launch_bounds__(256)
void k_layer1(const float* __restrict__ x,
              const float* __restrict__ W1l, const float* __restrict__ b1l,
              const float* __restrict__ W1r,
              const float* __restrict__ g1, const float* __restrict__ bb1,
              const float* __restrict__ m1, const float* __restrict__ v1) {
    extern __shared__ char smem_raw[];
    float* SIN = (float*)(smem_raw + L1_SIN);
    float* SW  = (float*)(smem_raw + L1_SW);
    float* SAL = (float*)(smem_raw + L1_ALPHA);
    float* SBE = (float*)(smem_raw + L1_BETA);

    int t = threadIdx.x;
    int nb = blockIdx.x * 128;

    // Stage inputs node-major [m][k], K=64 = [agg1(32) | x(32)], float4 stores
#pragma unroll
    for (int it = 0; it < 8; it++) {
        int f = t + 256 * it;            // float4 id [0,2048)
        int m = f >> 4, c = f & 15;
        int n = nb + m; int nc = n < NN ? n : NN - 1;
        float4 v; int k;
        if (c < 8) { v = __ldg((const float4*)&g_agg1[(long long)nc * INC] + c); k = c * 4; }
        else       { v = __ldg((const float4*)&x[(long long)nc * INC] + (c - 8)); k = 32 + (c - 8) * 4; }
        *(float4*)&SIN[m * L1_PAD + k] = v;
    }
#pragma unroll
    for (int it = 0; it < 4; it++) {
        int f4 = t + 256 * it;           // [0,1024)
        float4 v = (f4 < 512) ? __ldg((const float4*)W1l + f4)
                              : __ldg((const float4*)W1r + (f4 - 512));
        ((float4*)SW)[f4] = v;
    }
    if (t < HIDC) {
        float a = g1[t] * rsqrtf(v1[t] + 1e-5f);
        SAL[t] = a;
        SBE[t] = (b1l[t] - m1[t]) * a + bb1[t];
    }
    __syncthreads();

    int tn = t & 7, tm = t >> 3;         // tm in [0,32)
    const float* sinb = &SIN[(tm * 4) * L1_PAD];
    const ulonglong2* swu = (const ulonglong2*)SW;

    unsigned long long acc[16];
#pragma unroll
    for (int i = 0; i < 16; i++) acc[i] = 0ull;

#pragma unroll 4
    for (int k4 = 0; k4 < 16; k4++) {
        float4 a4[4];
#pragma unroll
        for (int i = 0; i < 4; i++)
            a4[i] = *(const float4*)&sinb[i * L1_PAD + k4 * 4];
#pragma unroll
        for (int kk = 0; kk < 4; kk++) {
            int k = k4 * 4 + kk;
            ulonglong2 wA = swu[k * 16 + tn * 2];
            ulonglong2 wB = swu[k * 16 + tn * 2 + 1];
#pragma unroll
            for (int i = 0; i < 4; i++) {
                float av = ((const float*)&a4[i])[kk];
                unsigned long long ad = pack2(av, av);
                FMA2(acc[i*4+0], ad, wA.x);
                FMA2(acc[i*4+1], ad, wA.y);
                FMA2(acc[i*4+2], ad, wB.x);
                FMA2(acc[i*4+3], ad, wB.y);
            }
        }
    }

    float al[8], be[8];
#pragma unroll
    for (int j = 0; j < 8; j++) { al[j] = SAL[tn*8+j]; be[j] = SBE[tn*8+j]; }
#pragma unroll
    for (int i = 0; i < 4; i++) {
        int n = nb + tm * 4 + i;
        if (n < NN) {
            float r[8];
#pragma unroll
            for (int p = 0; p < 4; p++) unpack2(r[2*p], r[2*p+1], acc[i*4+p]);
#pragma unroll
            for (int j = 0; j < 8; j++) r[j] = fmaxf(r[j] * al[j] + be[j], 0.f);
            __half2 h0 = __floats2half2_rn(r[0], r[1]);
            __half2 h1 = __floats2half2_rn(r[2], r[3]);
            __half2 h2 = __floats2half2_rn(r[4], r[5]);
            __half2 h3 = __floats2half2_rn(r[6], r[7]);
            uint4 pkt;
            pkt.x = *(unsigned int*)&h0;
            pkt.y = *(unsigned int*)&h1;
            pkt.z = *(unsigned int*)&h2;
            pkt.w = *(unsigned int*)&h3;
            ((uint4*)g_h)[n * 8 + tn] = pkt;
        }
    }
}

// ============================================================================
// Layer 2 + head: h2 = relu(bn2([agg2h | h] @ [W2l;W2r])); out = h2 @ Wlin + b
// PAD=132; both input halves staged from fp16.
// ============================================================================
#define L2_PAD   132
#define L2_SIN   0
#define L2_SW    (128 * L2_PAD * 4)          // 67584
#define L2_ALPHA (L2_SW + 128 * 64 * 4)      // +32768
#define L2_BETA  (L2_ALPHA + 256)
#define L2_SWO   (L2_BETA + 256)
#define L2_SMEM  (L2_SWO + 256)              // 101120

__global__ __launch_bounds__(256)
void k_layer2(const float* __restrict__ W2l, const float* __restrict__ b2l,
              const float* __restrict__ W2r,
              const float* __restrict__ g2, const float* __restrict__ bb2,
              const float* __restrict__ m2, const float* __restrict__ v2,
              const float* __restrict__ Wlin, const float* __restrict__ blin,
              float* __restrict__ out) {
    extern __shared__ char smem_raw[];
    float* SIN = (float*)(smem_raw + L2_SIN);
    float* SW  = (float*)(smem_raw + L2_SW);
    float* SAL = (float*)(smem_raw + L2_ALPHA);
    float* SBE = (float*)(smem_raw + L2_BETA);
    float* SWO = (float*)(smem_raw + L2_SWO);

    int t = threadIdx.x;
    int nb = blockIdx.x * 128;

    // Stage agg2 (fp16 -> f32): k = [0,64)
#pragma unroll
    for (int it = 0; it < 4; it++) {
        int f = t + 256 * it;            // uint4 id [0,1024)
        int m = f >> 3, g = f & 7;
        int n = nb + m; int nc = n < NN ? n : NN - 1;
        uint4 u = __ldg((const uint4*)g_agg2h + (nc * 8 + g));
        float2 f0 = __half22float2(*(__half2*)&u.x);
        float2 f1 = __half22float2(*(__half2*)&u.y);
        float2 f2 = __half22float2(*(__half2*)&u.z);
        float2 f3 = __half22float2(*(__half2*)&u.w);
        float* dp = &SIN[m * L2_PAD + g * 8];
        *(float4*)(dp + 0) = make_float4(f0.x, f0.y, f1.x, f1.y);
        *(float4*)(dp + 4) = make_float4(f2.x, f2.y, f3.x, f3.y);
    }
    // Stage h (fp16 -> f32): k = [64,128)
#pragma unroll
    for (int it = 0; it < 4; it++) {
        int f = t + 256 * it;            // uint4 id [0,1024)
        int m = f >> 3, g = f & 7;
        int n = nb + m; int nc = n < NN ? n : NN - 1;
        uint4 u = __ldg((const uint4*)g_h + (nc * 8 + g));
        float2 f0 = __half22float2(*(__half2*)&u.x);
        float2 f1 = __half22float2(*(__half2*)&u.y);
        float2 f2 = __half22float2(*(__half2*)&u.z);
        float2 f3 = __half22float2(*(__half2*)&u.w);
        float* dp = &SIN[m * L2_PAD + 64 + g * 8];
        *(float4*)(dp + 0) = make_float4(f0.x, f0.y, f1.x, f1.y);
        *(float4*)(dp + 4) = make_float4(f2.x, f2.y, f3.x, f3.y);
    }
#pragma unroll
    for (int it = 0; it < 8; it++) {
        int f4 = t + 256 * it;           // [0,2048)
        float4 v = (f4 < 1024) ? __ldg((const float4*)W2l + f4)
                               : __ldg((const float4*)W2r + (f4 - 1024));
        ((float4*)SW)[f4] = v;
    }
    if (t < HIDC) {
        float a = g2[t] * rsqrtf(v2[t] + 1e-5f);
        SAL[t] = a;
        SBE[t] = (b2l[t] - m2[t]) * a + bb2[t];
        SWO[t] = Wlin[t];
    }
    __syncthreads();

    int tn = t & 7, tm = t >> 3;
    const float* sinb = &SIN[(tm * 4) * L2_PAD];
    const ulonglong2* swu = (const ulonglong2*)SW;

    unsigned long long acc[16];
#pragma unroll
    for (int i = 0; i < 16; i++) acc[i] = 0ull;

#pragma unroll 4
    for (int k4 = 0; k4 < 32; k4++) {
        float4 a4[4];
#pragma unroll
        for (int i = 0; i < 4; i++)
            a4[i] = *(const float4*)&sinb[i * L2_PAD + k4 * 4];
#pragma unroll
        for (int kk = 0; kk < 4; kk++) {
            int k = k4 * 4 + kk;
            ulonglong2 wA = swu[k * 16 + tn * 2];
            ulonglong2 wB = swu[k * 16 + tn * 2 + 1];
#pragma unroll
            for (int i = 0; i < 4; i++) {
                float av = ((const float*)&a4[i])[kk];
                unsigned long long ad = pack2(av, av);
                FMA2(acc[i*4+0], ad, wA.x);
                FMA2(acc[i*4+1], ad, wA.y);
                FMA2(acc[i*4+2], ad, wB.x);
                FMA2(acc[i*4+3], ad, wB.y);
            }
        }
    }

    // BN + ReLU + head dot; reduce across the 8 tn lanes (same warp)
    float al[8], be[8], wo[8];
#pragma unroll
    for (int j = 0; j < 8; j++) {
        al[j] = SAL[tn*8+j]; be[j] = SBE[tn*8+j]; wo[j] = SWO[tn*8+j];
    }
    float part[4];
#pragma unroll
    for (int i = 0; i < 4; i++) {
        float r[8];
#pragma unroll
        for (int p = 0; p < 4; p++) unpack2(r[2*p], r[2*p+1], acc[i*4+p]);
        float s = 0.f;
#pragma unroll
        for (int j = 0; j < 8; j++)
            s += fmaxf(r[j] * al[j] + be[j], 0.f) * wo[j];
        part[i] = s;
    }
#pragma unroll
    for (int i = 0; i < 4; i++) {
        part[i] += __shfl_xor_sync(0xFFFFFFFFu, part[i], 1);
        part[i] += __shfl_xor_sync(0xFFFFFFFFu, part[i], 2);
        part[i] += __shfl_xor_sync(0xFFFFFFFFu, part[i], 4);
    }
    if (tn == 0) {
        float b0 = __ldg(&blin[0]);
#pragma unroll
        for (int i = 0; i < 4; i++) {
            int n = nb + tm * 4 + i;
            if (n < NN) out[n] = part[i] + b0;
        }
    }
}

// ============================================================================
// Launch — 5 kernels
// ============================================================================
extern "C" void kernel_launch(void* const* d_in, const int* in_sizes, int n_in,
                              void* d_out, int out_size) {
    const float* x   = (const float*)d_in[0];
    const int*   ei  = (const int*)d_in[1];   // int32 (jax x64 disabled)
    const int*   src = ei;
    const int*   dst = ei + EE;
    const float* W1l  = (const float*)d_in[2];
    const float* b1l  = (const float*)d_in[3];
    const float* W1r  = (const float*)d_in[4];
    const float* bn1g = (const float*)d_in[5];
    const float* bn1b = (const float*)d_in[6];
    const float* bn1m = (const float*)d_in[7];
    const float* bn1v = (const float*)d_in[8];
    const float* W2l  = (const float*)d_in[9];
    const float* b2l  = (const float*)d_in[10];
    const float* W2r  = (const float*)d_in[11];
    const float* bn2g = (const float*)d_in[12];
    const float* bn2b = (const float*)d_in[13];
    const float* bn2m = (const float*)d_in[14];
    const float* bn2v = (const float*)d_in[15];
    const float* Wlin = (const float*)d_in[16];
    const float* blin = (const float*)d_in[17];
    float* out = (float*)d_out;

    cudaFuncSetAttribute(k_layer1, cudaFuncAttributeMaxDynamicSharedMemorySize, L1_SMEM);
    cudaFuncSetAttribute(k_layer2, cudaFuncAttributeMaxDynamicSharedMemorySize, L2_SMEM);

    int nblk  = (NN + 127) / 128;            // 391
    int a1blk = (NN * 8 + 255) / 256;        // 1563  (4 nodes/warp)
    int a2blk = (NN * 8 + 255) / 256;        // 1563  (4 nodes/warp)

    k_fill<<<(EE / 8 + 255) / 256, 256>>>(src, dst);
    k_agg1<<<a1blk, 256>>>(x);
    k_layer1<<<nblk, 256, L1_SMEM>>>(x, W1l, b1l, W1r, bn1g, bn1b, bn1m, bn1v);
    k_agg2<<<a2blk, 256>>>();
    k_layer2<<<nblk, 256, L2_SMEM>>>(W2l, b2l, W2r, bn2g, bn2b, bn2m, bn2v,
                                     Wlin, blin, out);
}

// round 12
// speedup vs baseline: 1.1486x; 1.1486x over previous
#include <cuda_runtime.h>
#include <cuda_fp16.h>

#define NN   50000
#define EE   800000
#define INC  32
#define HIDC 64
#define MAXDEG 96

// -------------------- device scratch (no allocation allowed) ----------------
// Invariant: g_cnt is ZERO at entry of every kernel_launch call
// (zeroed at module load; restored by k_agg2 each call).
__device__ __align__(16) int    g_cnt[NN];            // degree + fill cursor
__device__ __align__(16) int    g_csrp[NN * MAXDEG];  // padded CSR: src by dst
__device__ __align__(16) float  g_agg1[NN * INC];     // normalized mean of x
__device__ __align__(16) __half g_agg2h[NN * HIDC];   // normalized mean of h (fp16)
__device__ __align__(16) __half g_h[NN * HIDC];       // layer-1 output (fp16)

// -------------------- f32x2 packed math helpers -----------------------------
__device__ __forceinline__ unsigned long long pack2(float lo, float hi) {
    unsigned long long r;
    asm("mov.b64 %0, {%1, %2};" : "=l"(r) : "f"(lo), "f"(hi));
    return r;
}
__device__ __forceinline__ void unpack2(float& lo, float& hi, unsigned long long v) {
    asm("mov.b64 {%0, %1}, %2;" : "=f"(lo), "=f"(hi) : "l"(v));
}
#define FMA2(d, a, b) asm("fma.rn.f32x2 %0, %1, %2, %0;" : "+l"(d) : "l"(a), "l"(b))

// ============================================================================
// Padded-CSR fill: 4 edges per thread (int4 loads, 4 independent atomic chains)
// ============================================================================
__global__ __launch_bounds__(256)
void k_fill(const int* __restrict__ src, const int* __restrict__ dst) {
    int q = blockIdx.x * blockDim.x + threadIdx.x;   // quad id
    if (q >= EE / 4) return;
    int4 s4 = __ldg((const int4*)src + q);
    int4 d4 = __ldg((const int4*)dst + q);
    int sl0 = atomicAdd(&g_cnt[d4.x], 1);
    int sl1 = atomicAdd(&g_cnt[d4.y], 1);
    int sl2 = atomicAdd(&g_cnt[d4.z], 1);
    int sl3 = atomicAdd(&g_cnt[d4.w], 1);
    if (sl0 < MAXDEG) g_csrp[d4.x * MAXDEG + sl0] = s4.x;
    if (sl1 < MAXDEG) g_csrp[d4.y * MAXDEG + sl1] = s4.y;
    if (sl2 < MAXDEG) g_csrp[d4.z * MAXDEG + sl2] = s4.z;
    if (sl3 < MAXDEG) g_csrp[d4.w * MAXDEG + sl3] = s4.w;
}

// ============================================================================
// Agg 1: 4 nodes per warp; 8 lanes x float4 cover the 32 channels.
// Indices loaded as int4 (CSR rows are 16B-aligned).
// ============================================================================
__global__ __launch_bounds__(256)
void k_agg1(const float* __restrict__ x) {
    int gt   = blockIdx.x * blockDim.x + threadIdx.x;
    int wid  = gt >> 5;
    int lane = gt & 31;
    int sub  = lane >> 3;        // node within warp (0..3)
    int c4   = lane & 7;         // float4 channel group (0..7)
    int n = wid * 4 + sub;
    if (n >= NN) return;

    int deg  = g_cnt[n];
    int degc = deg < MAXDEG ? deg : MAXDEG;
    const int*    row = &g_csrp[n * MAXDEG];
    const float4* xp  = (const float4*)x;

    float4 acc = make_float4(0.f, 0.f, 0.f, 0.f);
    int j = 0;
    for (; j + 3 < degc; j += 4) {
        int4 s = __ldg((const int4*)(row + j));
        float4 v0 = __ldg(xp + (s.x * 8 + c4));
        float4 v1 = __ldg(xp + (s.y * 8 + c4));
        float4 v2 = __ldg(xp + (s.z * 8 + c4));
        float4 v3 = __ldg(xp + (s.w * 8 + c4));
        acc.x += (v0.x + v1.x) + (v2.x + v3.x);
        acc.y += (v0.y + v1.y) + (v2.y + v3.y);
        acc.z += (v0.z + v1.z) + (v2.z + v3.z);
        acc.w += (v0.w + v1.w) + (v2.w + v3.w);
    }
    for (; j < degc; j++) {
        float4 v = __ldg(xp + (__ldg(row + j) * 8 + c4));
        acc.x += v.x; acc.y += v.y; acc.z += v.z; acc.w += v.w;
    }
    float dinv = 1.0f / fmaxf((float)deg, 1.0f);
    acc.x *= dinv; acc.y *= dinv; acc.z *= dinv; acc.w *= dinv;
    ((float4*)g_agg1)[n * 8 + c4] = acc;
}

// ============================================================================
// Agg 2: 4 nodes per warp; 8 lanes x uint4 (8 fp16) cover the 64 channels.
// Indices as int4; main loop 8 neighbors deep. fp16 output.
// Also restores g_cnt[n] = 0 for the next invocation (last reader of deg).
// ============================================================================
__global__ __launch_bounds__(256)
void k_agg2() {
    int gt   = blockIdx.x * blockDim.x + threadIdx.x;
    int wid  = gt >> 5;
    int lane = gt & 31;
    int sub  = lane >> 3;        // node within warp (0..3)
    int c8   = lane & 7;         // 8-halves group (0..7)
    int n = wid * 4 + sub;
    if (n >= NN) return;

    int deg  = g_cnt[n];
    int degc = deg < MAXDEG ? deg : MAXDEG;
    const int*   row = &g_csrp[n * MAXDEG];
    const uint4* hp  = (const uint4*)g_h;    // 8 halves per uint4

    float acc[8];
#pragma unroll
    for (int i = 0; i < 8; i++) acc[i] = 0.f;

    int j = 0;
    for (; j + 7 < degc; j += 8) {
        int4 sA = __ldg((const int4*)(row + j));
        int4 sB = __ldg((const int4*)(row + j + 4));
        uint4 u0 = __ldg(hp + (sA.x * 8 + c8));
        uint4 u1 = __ldg(hp + (sA.y * 8 + c8));
        uint4 u2 = __ldg(hp + (sA.z * 8 + c8));
        uint4 u3 = __ldg(hp + (sA.w * 8 + c8));
        uint4 u4 = __ldg(hp + (sB.x * 8 + c8));
        uint4 u5 = __ldg(hp + (sB.y * 8 + c8));
        uint4 u6 = __ldg(hp + (sB.z * 8 + c8));
        uint4 u7 = __ldg(hp + (sB.w * 8 + c8));
#pragma unroll
        for (int q = 0; q < 8; q++) {
            uint4 u = (q == 0) ? u0 : (q == 1) ? u1 : (q == 2) ? u2 :
                      (q == 3) ? u3 : (q == 4) ? u4 : (q == 5) ? u5 :
                      (q == 6) ? u6 : u7;
            float2 f0 = __half22float2(*(__half2*)&u.x);
            float2 f1 = __half22float2(*(__half2*)&u.y);
            float2 f2 = __half22float2(*(__half2*)&u.z);
            float2 f3 = __half22float2(*(__half2*)&u.w);
            acc[0] += f0.x; acc[1] += f0.y;
            acc[2] += f1.x; acc[3] += f1.y;
            acc[4] += f2.x; acc[5] += f2.y;
            acc[6] += f3.x; acc[7] += f3.y;
        }
    }
    for (; j + 3 < degc; j += 4) {
        int4 s = __ldg((const int4*)(row + j));
        uint4 u0 = __ldg(hp + (s.x * 8 + c8));
        uint4 u1 = __ldg(hp + (s.y * 8 + c8));
        uint4 u2 = __ldg(hp + (s.z * 8 + c8));
        uint4 u3 = __ldg(hp + (s.w * 8 + c8));
#pragma unroll
        for (int q = 0; q < 4; q++) {
            uint4 u = (q == 0) ? u0 : (q == 1) ? u1 : (q == 2) ? u2 : u3;
            float2 f0 = __half22float2(*(__half2*)&u.x);
            float2 f1 = __half22float2(*(__half2*)&u.y);
            float2 f2 = __half22float2(*(__half2*)&u.z);
            float2 f3 = __half22float2(*(__half2*)&u.w);
            acc[0] += f0.x; acc[1] += f0.y;
            acc[2] += f1.x; acc[3] += f1.y;
            acc[4] += f2.x; acc[5] += f2.y;
            acc[6] += f3.x; acc[7] += f3.y;
        }
    }
    for (; j < degc; j++) {
        uint4 u = __ldg(hp + (__ldg(row + j) * 8 + c8));
        float2 f0 = __half22float2(*(__half2*)&u.x);
        float2 f1 = __half22float2(*(__half2*)&u.y);
        float2 f2 = __half22float2(*(__half2*)&u.z);
        float2 f3 = __half22float2(*(__half2*)&u.w);
        acc[0] += f0.x; acc[1] += f0.y;
        acc[2] += f1.x; acc[3] += f1.y;
        acc[4] += f2.x; acc[5] += f2.y;
        acc[6] += f3.x; acc[7] += f3.y;
    }
    float dinv = 1.0f / fmaxf((float)deg, 1.0f);
    __half2 p0 = __floats2half2_rn(acc[0]*dinv, acc[1]*dinv);
    __half2 p1 = __floats2half2_rn(acc[2]*dinv, acc[3]*dinv);
    __half2 p2 = __floats2half2_rn(acc[4]*dinv, acc[5]*dinv);
    __half2 p3 = __floats2half2_rn(acc[6]*dinv, acc[7]*dinv);
    uint4 pkt;
    pkt.x = *(unsigned int*)&p0;
    pkt.y = *(unsigned int*)&p1;
    pkt.z = *(unsigned int*)&p2;
    pkt.w = *(unsigned int*)&p3;
    ((uint4*)g_agg2h)[n * 8 + c8] = pkt;
    if (c8 == 0) g_cnt[n] = 0;   // restore invariant
}

// ============================================================================
// Layer 1 GEMM: h[n][o] = relu(a1[o]*([agg1 | x] @ [W1l;W1r])[n][o] + b1[o])
// 128 nodes x 64 outs, 256 threads, 4x8 tile (f32x2). PAD=65 (conflict-free).
// Output stored fp16.
// ============================================================================
#define L1_PAD   65
#define L1_SIN   0
#define L1_SW    (128 * L1_PAD * 4)          // 33280
#define L1_ALPHA (L1_SW + 64 * 64 * 4)       // +16384
#define L1_BETA  (L1_ALPHA + 256)
#define L1_SMEM  (L1_BETA + 256)             // 50176

__global__ __launch_bounds__(256)
void k_layer1(const float* __restrict__ x,
              const float* __restrict__ W1l, const float* __restrict__ b1l,
              const float* __restrict__ W1r,
              const float* __restrict__ g1, const float* __restrict__ bb1,
              const float* __restrict__ m1, const float* __restrict__ v1) {
    extern __shared__ char smem_raw[];
    float* SIN = (float*)(smem_raw + L1_SIN);
    float* SW  = (float*)(smem_raw + L1_SW);
    float* SAL = (float*)(smem_raw + L1_ALPHA);
    float* SBE = (float*)(smem_raw + L1_BETA);

    int t = threadIdx.x;
    int nb = blockIdx.x * 128;

    // Stage inputs node-major [m][k], K=64 = [agg1(32) | x(32)]
#pragma unroll
    for (int it = 0; it < 8; it++) {
        int f = t + 256 * it;            // float4 id [0,2048)
        int m = f >> 4, c = f & 15;
        int n = nb + m; int nc = n < NN ? n : NN - 1;
        float4 v; int k;
        if (c < 8) { v = __ldg((const float4*)&g_agg1[(long long)nc * INC] + c); k = c * 4; }
        else       { v = __ldg((const float4*)&x[(long long)nc * INC] + (c - 8)); k = 32 + (c - 8) * 4; }
        float* dp = &SIN[m * L1_PAD + k];
        dp[0] = v.x; dp[1] = v.y; dp[2] = v.z; dp[3] = v.w;
    }
#pragma unroll
    for (int it = 0; it < 4; it++) {
        int f4 = t + 256 * it;           // [0,1024)
        float4 v = (f4 < 512) ? __ldg((const float4*)W1l + f4)
                              : __ldg((const float4*)W1r + (f4 - 512));
        ((float4*)SW)[f4] = v;
    }
    if (t < HIDC) {
        float a = g1[t] * rsqrtf(v1[t] + 1e-5f);
        SAL[t] = a;
        SBE[t] = (b1l[t] - m1[t]) * a + bb1[t];
    }
    __syncthreads();

    int tn = t & 7, tm = t >> 3;         // tm in [0,32)
    const float* sinb = &SIN[(tm * 4) * L1_PAD];
    const ulonglong2* swu = (const ulonglong2*)SW;

    unsigned long long acc[16];
#pragma unroll
    for (int i = 0; i < 16; i++) acc[i] = 0ull;

#pragma unroll 4
    for (int k = 0; k < 64; k++) {
        unsigned long long ad[4];
#pragma unroll
        for (int i = 0; i < 4; i++) {
            float av = sinb[i * L1_PAD + k];
            ad[i] = pack2(av, av);
        }
        ulonglong2 wA = swu[k * 16 + tn * 2];
        ulonglong2 wB = swu[k * 16 + tn * 2 + 1];
#pragma unroll
        for (int i = 0; i < 4; i++) {
            FMA2(acc[i*4+0], ad[i], wA.x);
            FMA2(acc[i*4+1], ad[i], wA.y);
            FMA2(acc[i*4+2], ad[i], wB.x);
            FMA2(acc[i*4+3], ad[i], wB.y);
        }
    }

    float al[8], be[8];
#pragma unroll
    for (int j = 0; j < 8; j++) { al[j] = SAL[tn*8+j]; be[j] = SBE[tn*8+j]; }
#pragma unroll
    for (int i = 0; i < 4; i++) {
        int n = nb + tm * 4 + i;
        if (n < NN) {
            float r[8];
#pragma unroll
            for (int p = 0; p < 4; p++) unpack2(r[2*p], r[2*p+1], acc[i*4+p]);
#pragma unroll
            for (int j = 0; j < 8; j++) r[j] = fmaxf(r[j] * al[j] + be[j], 0.f);
            __half2 h0 = __floats2half2_rn(r[0], r[1]);
            __half2 h1 = __floats2half2_rn(r[2], r[3]);
            __half2 h2 = __floats2half2_rn(r[4], r[5]);
            __half2 h3 = __floats2half2_rn(r[6], r[7]);
            uint4 pkt;
            pkt.x = *(unsigned int*)&h0;
            pkt.y = *(unsigned int*)&h1;
            pkt.z = *(unsigned int*)&h2;
            pkt.w = *(unsigned int*)&h3;
            ((uint4*)g_h)[n * 8 + tn] = pkt;
        }
    }
}

// ============================================================================
// Layer 2 + head: h2 = relu(bn2([agg2h | h] @ [W2l;W2r])); out = h2 @ Wlin + b
// PAD=129 (conflict-free). Both input halves staged from fp16.
// ============================================================================
#define L2_PAD   129
#define L2_SIN   0
#define L2_SW    (128 * L2_PAD * 4)          // 66048
#define L2_ALPHA (L2_SW + 128 * 64 * 4)      // +32768
#define L2_BETA  (L2_ALPHA + 256)
#define L2_SWO   (L2_BETA + 256)
#define L2_SMEM  (L2_SWO + 256)              // 99584

__global__ __launch_bounds__(256)
void k_layer2(const float* __restrict__ W2l, const float* __restrict__ b2l,
              const float* __restrict__ W2r,
              const float* __restrict__ g2, const float* __restrict__ bb2,
              const float* __restrict__ m2, const float* __restrict__ v2,
              const float* __restrict__ Wlin, const float* __restrict__ blin,
              float* __restrict__ out) {
    extern __shared__ char smem_raw[];
    float* SIN = (float*)(smem_raw + L2_SIN);
    float* SW  = (float*)(smem_raw + L2_SW);
    float* SAL = (float*)(smem_raw + L2_ALPHA);
    float* SBE = (float*)(smem_raw + L2_BETA);
    float* SWO = (float*)(smem_raw + L2_SWO);

    int t = threadIdx.x;
    int nb = blockIdx.x * 128;

    // Stage agg2 (fp16 -> f32): k = [0,64)
#pragma unroll
    for (int it = 0; it < 4; it++) {
        int f = t + 256 * it;            // uint4 id [0,1024)
        int m = f >> 3, g = f & 7;
        int n = nb + m; int nc = n < NN ? n : NN - 1;
        uint4 u = __ldg((const uint4*)g_agg2h + (nc * 8 + g));
        float2 f0 = __half22float2(*(__half2*)&u.x);
        float2 f1 = __half22float2(*(__half2*)&u.y);
        float2 f2 = __half22float2(*(__half2*)&u.z);
        float2 f3 = __half22float2(*(__half2*)&u.w);
        float* dp = &SIN[m * L2_PAD + g * 8];
        dp[0] = f0.x; dp[1] = f0.y; dp[2] = f1.x; dp[3] = f1.y;
        dp[4] = f2.x; dp[5] = f2.y; dp[6] = f3.x; dp[7] = f3.y;
    }
    // Stage h (fp16 -> f32): k = [64,128)
#pragma unroll
    for (int it = 0; it < 4; it++) {
        int f = t + 256 * it;            // uint4 id [0,1024)
        int m = f >> 3, g = f & 7;
        int n = nb + m; int nc = n < NN ? n : NN - 1;
        uint4 u = __ldg((const uint4*)g_h + (nc * 8 + g));
        float2 f0 = __half22float2(*(__half2*)&u.x);
        float2 f1 = __half22float2(*(__half2*)&u.y);
        float2 f2 = __half22float2(*(__half2*)&u.z);
        float2 f3 = __half22float2(*(__half2*)&u.w);
        float* dp = &SIN[m * L2_PAD + 64 + g * 8];
        dp[0] = f0.x; dp[1] = f0.y; dp[2] = f1.x; dp[3] = f1.y;
        dp[4] = f2.x; dp[5] = f2.y; dp[6] = f3.x; dp[7] = f3.y;
    }
#pragma unroll
    for (int it = 0; it < 8; it++) {
        int f4 = t + 256 * it;           // [0,2048)
        float4 v = (f4 < 1024) ? __ldg((const float4*)W2l + f4)
                               : __ldg((const float4*)W2r + (f4 - 1024));
        ((float4*)SW)[f4] = v;
    }
    if (t < HIDC) {
        float a = g2[t] * rsqrtf(v2[t] + 1e-5f);
        SAL[t] = a;
        SBE[t] = (b2l[t] - m2[t]) * a + bb2[t];
        SWO[t] = Wlin[t];
    }
    __syncthreads();

    int tn = t & 7, tm = t >> 3;
    const float* sinb = &SIN[(tm * 4) * L2_PAD];
    const ulonglong2* swu = (const ulonglong2*)SW;

    unsigned long long acc[16];
#pragma unroll
    for (int i = 0; i < 16; i++) acc[i] = 0ull;

#pragma unroll 4
    for (int k = 0; k < 128; k++) {
        unsigned long long ad[4];
#pragma unroll
        for (int i = 0; i < 4; i++) {
            float av = sinb[i * L2_PAD + k];
            ad[i] = pack2(av, av);
        }
        ulonglong2 wA = swu[k * 16 + tn * 2];
        ulonglong2 wB = swu[k * 16 + tn * 2 + 1];
#pragma unroll
        for (int i = 0; i < 4; i++) {
            FMA2(acc[i*4+0], ad[i], wA.x);
            FMA2(acc[i*4+1], ad[i], wA.y);
            FMA2(acc[i*4+2], ad[i], wB.x);
            FMA2(acc[i*4+3], ad[i], wB.y);
        }
    }

    // BN + ReLU + head dot; reduce across the 8 tn lanes (same warp)
    float al[8], be[8], wo[8];
#pragma unroll
    for (int j = 0; j < 8; j++) {
        al[j] = SAL[tn*8+j]; be[j] = SBE[tn*8+j]; wo[j] = SWO[tn*8+j];
    }
    float part[4];
#pragma unroll
    for (int i = 0; i < 4; i++) {
        float r[8];
#pragma unroll
        for (int p = 0; p < 4; p++) unpack2(r[2*p], r[2*p+1], acc[i*4+p]);
        float s = 0.f;
#pragma unroll
        for (int j = 0; j < 8; j++)
            s += fmaxf(r[j] * al[j] + be[j], 0.f) * wo[j];
        part[i] = s;
    }
#pragma unroll
    for (int i = 0; i < 4; i++) {
        part[i] += __shfl_xor_sync(0xFFFFFFFFu, part[i], 1);
        part[i] += __shfl_xor_sync(0xFFFFFFFFu, part[i], 2);
        part[i] += __shfl_xor_sync(0xFFFFFFFFu, part[i], 4);
    }
    if (tn == 0) {
        float b0 = __ldg(&blin[0]);
#pragma unroll
        for (int i = 0; i < 4; i++) {
            int n = nb + tm * 4 + i;
            if (n < NN) out[n] = part[i] + b0;
        }
    }
}

// ============================================================================
// Launch — 5 kernels
// ============================================================================
extern "C" void kernel_launch(void* const* d_in, const int* in_sizes, int n_in,
                              void* d_out, int out_size) {
    const float* x   = (const float*)d_in[0];
    const int*   ei  = (const int*)d_in[1];   // int32 (jax x64 disabled)
    const int*   src = ei;
    const int*   dst = ei + EE;
    const float* W1l  = (const float*)d_in[2];
    const float* b1l  = (const float*)d_in[3];
    const float* W1r  = (const float*)d_in[4];
    const float* bn1g = (const float*)d_in[5];
    const float* bn1b = (const float*)d_in[6];
    const float* bn1m = (const float*)d_in[7];
    const float* bn1v = (const float*)d_in[8];
    const float* W2l  = (const float*)d_in[9];
    const float* b2l  = (const float*)d_in[10];
    const float* W2r  = (const float*)d_in[11];
    const float* bn2g = (const float*)d_in[12];
    const float* bn2b = (const float*)d_in[13];
    const float* bn2m = (const float*)d_in[14];
    const float* bn2v = (const float*)d_in[15];
    const float* Wlin = (const float*)d_in[16];
    const float* blin = (const float*)d_in[17];
    float* out = (float*)d_out;

    cudaFuncSetAttribute(k_layer1, cudaFuncAttributeMaxDynamicSharedMemorySize, L1_SMEM);
    cudaFuncSetAttribute(k_layer2, cudaFuncAttributeMaxDynamicSharedMemorySize, L2_SMEM);

    int nblk  = (NN + 127) / 128;            // 391
    int a1blk = (NN * 8 + 255) / 256;        // 1563  (4 nodes/warp)
    int a2blk = (NN * 8 + 255) / 256;        // 1563  (4 nodes/warp)

    k_fill<<<(EE / 4 + 255) / 256, 256>>>(src, dst);
    k_agg1<<<a1blk, 256>>>(x);
    k_layer1<<<nblk, 256, L1_SMEM>>>(x, W1l, b1l, W1r, bn1g, bn1b, bn1m, bn1v);
    k_agg2<<<a2blk, 256>>>();
    k_layer2<<<nblk, 256, L2_SMEM>>>(W2l, b2l, W2r, bn2g, bn2b, bn2m, bn2v,
                                     Wlin, blin, out);
}

// round 13
// speedup vs baseline: 1.6015x; 1.3943x over previous
#include <cuda_runtime.h>
#include <cuda_fp16.h>

#define NN   50000
#define EE   800000
#define INC  32
#define HIDC 64
#define MAXDEG 96

// -------------------- device scratch (no allocation allowed) ----------------
// Invariant: g_cnt is ZERO at entry of every kernel_launch call
// (zeroed at module load; restored by k_agg2 each call).
__device__ __align__(16) int    g_cnt[NN];            // degree + fill cursor
__device__ __align__(16) int    g_csrp[NN * MAXDEG];  // padded CSR: src by dst
__device__ __align__(16) float  g_agg1[NN * INC];     // normalized mean of x
__device__ __align__(16) __half g_agg2h[NN * HIDC];   // normalized mean of h (fp16)
__device__ __align__(16) __half g_h[NN * HIDC];       // layer-1 output (fp16)

// -------------------- f32x2 packed math helpers -----------------------------
__device__ __forceinline__ unsigned long long pack2(float lo, float hi) {
    unsigned long long r;
    asm("mov.b64 %0, {%1, %2};" : "=l"(r) : "f"(lo), "f"(hi));
    return r;
}
__device__ __forceinline__ void unpack2(float& lo, float& hi, unsigned long long v) {
    asm("mov.b64 {%0, %1}, %2;" : "=f"(lo), "=f"(hi) : "l"(v));
}
#define FMA2(d, a, b) asm("fma.rn.f32x2 %0, %1, %2, %0;" : "+l"(d) : "l"(a), "l"(b))

// -------------------- tensor-core helpers ------------------------------------
__device__ __forceinline__ void ldsm_x4(unsigned* r, unsigned addr) {
    asm volatile("ldmatrix.sync.aligned.m8n8.x4.shared.b16 {%0,%1,%2,%3}, [%4];"
                 : "=r"(r[0]), "=r"(r[1]), "=r"(r[2]), "=r"(r[3]) : "r"(addr));
}
__device__ __forceinline__ void ldsm_x2t(unsigned& r0, unsigned& r1, unsigned addr) {
    asm volatile("ldmatrix.sync.aligned.m8n8.x2.trans.shared.b16 {%0,%1}, [%2];"
                 : "=r"(r0), "=r"(r1) : "r"(addr));
}
__device__ __forceinline__ void mma16816(float* d, const unsigned* a,
                                         unsigned b0, unsigned b1) {
    asm volatile("mma.sync.aligned.m16n8k16.row.col.f32.f16.f16.f32 "
                 "{%0,%1,%2,%3}, {%4,%5,%6,%7}, {%8,%9}, {%0,%1,%2,%3};"
                 : "+f"(d[0]), "+f"(d[1]), "+f"(d[2]), "+f"(d[3])
                 : "r"(a[0]), "r"(a[1]), "r"(a[2]), "r"(a[3]), "r"(b0), "r"(b1));
}

// ============================================================================
// Padded-CSR fill: 4 edges per thread (int4 loads, 4 independent atomic chains)
// ============================================================================
__global__ __launch_bounds__(256)
void k_fill(const int* __restrict__ src, const int* __restrict__ dst) {
    int q = blockIdx.x * blockDim.x + threadIdx.x;   // quad id
    if (q >= EE / 4) return;
    int4 s4 = __ldg((const int4*)src + q);
    int4 d4 = __ldg((const int4*)dst + q);
    int sl0 = atomicAdd(&g_cnt[d4.x], 1);
    int sl1 = atomicAdd(&g_cnt[d4.y], 1);
    int sl2 = atomicAdd(&g_cnt[d4.z], 1);
    int sl3 = atomicAdd(&g_cnt[d4.w], 1);
    if (sl0 < MAXDEG) g_csrp[d4.x * MAXDEG + sl0] = s4.x;
    if (sl1 < MAXDEG) g_csrp[d4.y * MAXDEG + sl1] = s4.y;
    if (sl2 < MAXDEG) g_csrp[d4.z * MAXDEG + sl2] = s4.z;
    if (sl3 < MAXDEG) g_csrp[d4.w * MAXDEG + sl3] = s4.w;
}

// ============================================================================
// Agg 1: 4 nodes per warp; 8 lanes x float4 cover the 32 channels.
// ============================================================================
__global__ __launch_bounds__(256)
void k_agg1(const float* __restrict__ x) {
    int gt   = blockIdx.x * blockDim.x + threadIdx.x;
    int wid  = gt >> 5;
    int lane = gt & 31;
    int sub  = lane >> 3;        // node within warp (0..3)
    int c4   = lane & 7;         // float4 channel group (0..7)
    int n = wid * 4 + sub;
    if (n >= NN) return;

    int deg  = g_cnt[n];
    int degc = deg < MAXDEG ? deg : MAXDEG;
    const int*    row = &g_csrp[n * MAXDEG];
    const float4* xp  = (const float4*)x;

    float4 acc = make_float4(0.f, 0.f, 0.f, 0.f);
    int j = 0;
    for (; j + 3 < degc; j += 4) {
        int4 s = __ldg((const int4*)(row + j));
        float4 v0 = __ldg(xp + (s.x * 8 + c4));
        float4 v1 = __ldg(xp + (s.y * 8 + c4));
        float4 v2 = __ldg(xp + (s.z * 8 + c4));
        float4 v3 = __ldg(xp + (s.w * 8 + c4));
        acc.x += (v0.x + v1.x) + (v2.x + v3.x);
        acc.y += (v0.y + v1.y) + (v2.y + v3.y);
        acc.z += (v0.z + v1.z) + (v2.z + v3.z);
        acc.w += (v0.w + v1.w) + (v2.w + v3.w);
    }
    for (; j < degc; j++) {
        float4 v = __ldg(xp + (__ldg(row + j) * 8 + c4));
        acc.x += v.x; acc.y += v.y; acc.z += v.z; acc.w += v.w;
    }
    float dinv = 1.0f / fmaxf((float)deg, 1.0f);
    acc.x *= dinv; acc.y *= dinv; acc.z *= dinv; acc.w *= dinv;
    ((float4*)g_agg1)[n * 8 + c4] = acc;
}

// ============================================================================
// Agg 2: 4 nodes per warp; 8 lanes x uint4 (8 fp16) cover the 64 channels.
// fp16 output. Also restores g_cnt[n] = 0 (last reader of deg).
// ============================================================================
__global__ __launch_bounds__(256)
void k_agg2() {
    int gt   = blockIdx.x * blockDim.x + threadIdx.x;
    int wid  = gt >> 5;
    int lane = gt & 31;
    int sub  = lane >> 3;        // node within warp (0..3)
    int c8   = lane & 7;         // 8-halves group (0..7)
    int n = wid * 4 + sub;
    if (n >= NN) return;

    int deg  = g_cnt[n];
    int degc = deg < MAXDEG ? deg : MAXDEG;
    const int*   row = &g_csrp[n * MAXDEG];
    const uint4* hp  = (const uint4*)g_h;    // 8 halves per uint4

    float acc[8];
#pragma unroll
    for (int i = 0; i < 8; i++) acc[i] = 0.f;

    int j = 0;
    for (; j + 7 < degc; j += 8) {
        int4 sA = __ldg((const int4*)(row + j));
        int4 sB = __ldg((const int4*)(row + j + 4));
        uint4 u0 = __ldg(hp + (sA.x * 8 + c8));
        uint4 u1 = __ldg(hp + (sA.y * 8 + c8));
        uint4 u2 = __ldg(hp + (sA.z * 8 + c8));
        uint4 u3 = __ldg(hp + (sA.w * 8 + c8));
        uint4 u4 = __ldg(hp + (sB.x * 8 + c8));
        uint4 u5 = __ldg(hp + (sB.y * 8 + c8));
        uint4 u6 = __ldg(hp + (sB.z * 8 + c8));
        uint4 u7 = __ldg(hp + (sB.w * 8 + c8));
#pragma unroll
        for (int q = 0; q < 8; q++) {
            uint4 u = (q == 0) ? u0 : (q == 1) ? u1 : (q == 2) ? u2 :
                      (q == 3) ? u3 : (q == 4) ? u4 : (q == 5) ? u5 :
                      (q == 6) ? u6 : u7;
            float2 f0 = __half22float2(*(__half2*)&u.x);
            float2 f1 = __half22float2(*(__half2*)&u.y);
            float2 f2 = __half22float2(*(__half2*)&u.z);
            float2 f3 = __half22float2(*(__half2*)&u.w);
            acc[0] += f0.x; acc[1] += f0.y;
            acc[2] += f1.x; acc[3] += f1.y;
            acc[4] += f2.x; acc[5] += f2.y;
            acc[6] += f3.x; acc[7] += f3.y;
        }
    }
    for (; j + 3 < degc; j += 4) {
        int4 s = __ldg((const int4*)(row + j));
        uint4 u0 = __ldg(hp + (s.x * 8 + c8));
        uint4 u1 = __ldg(hp + (s.y * 8 + c8));
        uint4 u2 = __ldg(hp + (s.z * 8 + c8));
        uint4 u3 = __ldg(hp + (s.w * 8 + c8));
#pragma unroll
        for (int q = 0; q < 4; q++) {
            uint4 u = (q == 0) ? u0 : (q == 1) ? u1 : (q == 2) ? u2 : u3;
            float2 f0 = __half22float2(*(__half2*)&u.x);
            float2 f1 = __half22float2(*(__half2*)&u.y);
            float2 f2 = __half22float2(*(__half2*)&u.z);
            float2 f3 = __half22float2(*(__half2*)&u.w);
            acc[0] += f0.x; acc[1] += f0.y;
            acc[2] += f1.x; acc[3] += f1.y;
            acc[4] += f2.x; acc[5] += f2.y;
            acc[6] += f3.x; acc[7] += f3.y;
        }
    }
    for (; j < degc; j++) {
        uint4 u = __ldg(hp + (__ldg(row + j) * 8 + c8));
        float2 f0 = __half22float2(*(__half2*)&u.x);
        float2 f1 = __half22float2(*(__half2*)&u.y);
        float2 f2 = __half22float2(*(__half2*)&u.z);
        float2 f3 = __half22float2(*(__half2*)&u.w);
        acc[0] += f0.x; acc[1] += f0.y;
        acc[2] += f1.x; acc[3] += f1.y;
        acc[4] += f2.x; acc[5] += f2.y;
        acc[6] += f3.x; acc[7] += f3.y;
    }
    float dinv = 1.0f / fmaxf((float)deg, 1.0f);
    __half2 p0 = __floats2half2_rn(acc[0]*dinv, acc[1]*dinv);
    __half2 p1 = __floats2half2_rn(acc[2]*dinv, acc[3]*dinv);
    __half2 p2 = __floats2half2_rn(acc[4]*dinv, acc[5]*dinv);
    __half2 p3 = __floats2half2_rn(acc[6]*dinv, acc[7]*dinv);
    uint4 pkt;
    pkt.x = *(unsigned int*)&p0;
    pkt.y = *(unsigned int*)&p1;
    pkt.z = *(unsigned int*)&p2;
    pkt.w = *(unsigned int*)&p3;
    ((uint4*)g_agg2h)[n * 8 + c8] = pkt;
    if (c8 == 0) g_cnt[n] = 0;   // restore invariant
}

// ============================================================================
// Layer 1 GEMM: h[n][o] = relu(a1[o]*([agg1 | x] @ [W1l;W1r])[n][o] + b1[o])
// 128 nodes x 64 outs, 256 threads, 4x8 tile (f32x2). PAD=65 (conflict-free).
// Output stored fp16.
// ============================================================================
#define L1_PAD   65
#define L1_SIN   0
#define L1_SW    (128 * L1_PAD * 4)          // 33280
#define L1_ALPHA (L1_SW + 64 * 64 * 4)       // +16384
#define L1_BETA  (L1_ALPHA + 256)
#define L1_SMEM  (L1_BETA + 256)             // 50176

__global__ __launch_bounds__(256)
void k_layer1(const float* __restrict__ x,
              const float* __restrict__ W1l, const float* __restrict__ b1l,
              const float* __restrict__ W1r,
              const float* __restrict__ g1, const float* __restrict__ bb1,
              const float* __restrict__ m1, const float* __restrict__ v1) {
    extern __shared__ char smem_raw[];
    float* SIN = (float*)(smem_raw + L1_SIN);
    float* SW  = (float*)(smem_raw + L1_SW);
    float* SAL = (float*)(smem_raw + L1_ALPHA);
    float* SBE = (float*)(smem_raw + L1_BETA);

    int t = threadIdx.x;
    int nb = blockIdx.x * 128;

    // Stage inputs node-major [m][k], K=64 = [agg1(32) | x(32)]
#pragma unroll
    for (int it = 0; it < 8; it++) {
        int f = t + 256 * it;            // float4 id [0,2048)
        int m = f >> 4, c = f & 15;
        int n = nb + m; int nc = n < NN ? n : NN - 1;
        float4 v; int k;
        if (c < 8) { v = __ldg((const float4*)&g_agg1[(long long)nc * INC] + c); k = c * 4; }
        else       { v = __ldg((const float4*)&x[(long long)nc * INC] + (c - 8)); k = 32 + (c - 8) * 4; }
        float* dp = &SIN[m * L1_PAD + k];
        dp[0] = v.x; dp[1] = v.y; dp[2] = v.z; dp[3] = v.w;
    }
#pragma unroll
    for (int it = 0; it < 4; it++) {
        int f4 = t + 256 * it;           // [0,1024)
        float4 v = (f4 < 512) ? __ldg((const float4*)W1l + f4)
                              : __ldg((const float4*)W1r + (f4 - 512));
        ((float4*)SW)[f4] = v;
    }
    if (t < HIDC) {
        float a = g1[t] * rsqrtf(v1[t] + 1e-5f);
        SAL[t] = a;
        SBE[t] = (b1l[t] - m1[t]) * a + bb1[t];
    }
    __syncthreads();

    int tn = t & 7, tm = t >> 3;         // tm in [0,32)
    const float* sinb = &SIN[(tm * 4) * L1_PAD];
    const ulonglong2* swu = (const ulonglong2*)SW;

    unsigned long long acc[16];
#pragma unroll
    for (int i = 0; i < 16; i++) acc[i] = 0ull;

#pragma unroll 4
    for (int k = 0; k < 64; k++) {
        unsigned long long ad[4];
#pragma unroll
        for (int i = 0; i < 4; i++) {
            float av = sinb[i * L1_PAD + k];
            ad[i] = pack2(av, av);
        }
        ulonglong2 wA = swu[k * 16 + tn * 2];
        ulonglong2 wB = swu[k * 16 + tn * 2 + 1];
#pragma unroll
        for (int i = 0; i < 4; i++) {
            FMA2(acc[i*4+0], ad[i], wA.x);
            FMA2(acc[i*4+1], ad[i], wA.y);
            FMA2(acc[i*4+2], ad[i], wB.x);
            FMA2(acc[i*4+3], ad[i], wB.y);
        }
    }

    float al[8], be[8];
#pragma unroll
    for (int j = 0; j < 8; j++) { al[j] = SAL[tn*8+j]; be[j] = SBE[tn*8+j]; }
#pragma unroll
    for (int i = 0; i < 4; i++) {
        int n = nb + tm * 4 + i;
        if (n < NN) {
            float r[8];
#pragma unroll
            for (int p = 0; p < 4; p++) unpack2(r[2*p], r[2*p+1], acc[i*4+p]);
#pragma unroll
            for (int j = 0; j < 8; j++) r[j] = fmaxf(r[j] * al[j] + be[j], 0.f);
            __half2 h0 = __floats2half2_rn(r[0], r[1]);
            __half2 h1 = __floats2half2_rn(r[2], r[3]);
            __half2 h2 = __floats2half2_rn(r[4], r[5]);
            __half2 h3 = __floats2half2_rn(r[6], r[7]);
            uint4 pkt;
            pkt.x = *(unsigned int*)&h0;
            pkt.y = *(unsigned int*)&h1;
            pkt.z = *(unsigned int*)&h2;
            pkt.w = *(unsigned int*)&h3;
            ((uint4*)g_h)[n * 8 + tn] = pkt;
        }
    }
}

// ============================================================================
// Layer 2 + head via tensor cores (mma.sync m16n8k16, fp16 in, fp32 accum):
//   D[128x64] = A[128x128] @ Wcat[128x64];  A = [agg2h | h] (already fp16)
//   out[n] = relu(bn2(D)) @ Wlin + blin
// Block: 128 nodes, 256 threads (8 warps), warp w owns m-tile rows [16w,16w+16).
// SA: fp16 [m][k], stride 136 halves (ldmatrix conflict-free).
// SB: fp16 [k][n], stride 72 halves; B-frags via ldmatrix.x2.trans.
// ============================================================================
#define L2_KH    136                          // SA row stride (halves)
#define L2_NH    72                           // SB row stride (halves)
#define L2_SA    0                            // 128*136*2 = 34816
#define L2_SB    34816                        // 128*72*2  = 18432
#define L2_ALPHA (34816 + 18432)              // 53248
#define L2_BETA  (L2_ALPHA + 256)
#define L2_SWO   (L2_BETA + 256)
#define L2_SMEM  (L2_SWO + 256)               // 54016

__global__ __launch_bounds__(256)
void k_layer2(const float* __restrict__ W2l, const float* __restrict__ b2l,
              const float* __restrict__ W2r,
              const float* __restrict__ g2, const float* __restrict__ bb2,
              const float* __restrict__ m2, const float* __restrict__ v2,
              const float* __restrict__ Wlin, const float* __restrict__ blin,
              float* __restrict__ out) {
    extern __shared__ char smem_raw[];
    __half* SA = (__half*)(smem_raw + L2_SA);
    __half* SB = (__half*)(smem_raw + L2_SB);
    float* SAL = (float*)(smem_raw + L2_ALPHA);
    float* SBE = (float*)(smem_raw + L2_BETA);
    float* SWO = (float*)(smem_raw + L2_SWO);

    int t = threadIdx.x;
    int nb = blockIdx.x * 128;
    int lane = t & 31, w = t >> 5;

    // Stage SA [m][k] fp16: k[0,64) = agg2h, k[64,128) = h. Direct uint4 copy.
#pragma unroll
    for (int it = 0; it < 8; it++) {
        int f = t + 256 * it;            // uint4 id [0,2048)
        int m = f >> 4, g = f & 15;
        int n = nb + m; int nc = n < NN ? n : NN - 1;
        uint4 u = (g < 8) ? __ldg((const uint4*)g_agg2h + (nc * 8 + g))
                          : __ldg((const uint4*)g_h + (nc * 8 + (g - 8)));
        *(uint4*)&SA[m * L2_KH + g * 8] = u;
    }
    // Stage SB [k][n] fp16 from fp32 weights (layout already [k][n])
#pragma unroll
    for (int it = 0; it < 8; it++) {
        int f4 = t + 256 * it;           // float4 id [0,2048)
        int k = f4 >> 4, j = f4 & 15;
        float4 wv = (f4 < 1024) ? __ldg((const float4*)W2l + f4)
                                : __ldg((const float4*)W2r + (f4 - 1024));
        __half2 h01 = __floats2half2_rn(wv.x, wv.y);
        __half2 h23 = __floats2half2_rn(wv.z, wv.w);
        uint2 p;
        p.x = *(unsigned int*)&h01;
        p.y = *(unsigned int*)&h23;
        *(uint2*)&SB[k * L2_NH + j * 4] = p;
    }
    if (t < HIDC) {
        float a = g2[t] * rsqrtf(v2[t] + 1e-5f);
        SAL[t] = a;
        SBE[t] = (b2l[t] - m2[t]) * a + bb2[t];
        SWO[t] = Wlin[t];
    }
    __syncthreads();

    // MMA: warp w -> rows [16w, 16w+16)
    int m0 = w * 16;
    float d[8][4];
#pragma unroll
    for (int j = 0; j < 8; j++)
#pragma unroll
        for (int i = 0; i < 4; i++) d[j][i] = 0.f;

    int arow = m0 + (lane & 15);
    int akk  = (lane >> 4) * 8;
    int brow = lane & 15;

#pragma unroll
    for (int s = 0; s < 8; s++) {
        unsigned afr[4];
        unsigned aaddr = (unsigned)__cvta_generic_to_shared(
            &SA[arow * L2_KH + s * 16 + akk]);
        ldsm_x4(afr, aaddr);
#pragma unroll
        for (int j = 0; j < 8; j++) {
            unsigned b0, b1;
            unsigned baddr = (unsigned)__cvta_generic_to_shared(
                &SB[(s * 16 + brow) * L2_NH + j * 8]);
            ldsm_x2t(b0, b1, baddr);
            mma16816(d[j], afr, b0, b1);
        }
    }

    // Epilogue: BN + ReLU + head dot on D fragments.
    // Thread holds rows (m0 + r0) and (m0 + r0 + 8), cols 8j + cbase + {0,1}.
    int r0 = lane >> 2;
    int cbase = 2 * (lane & 3);
    float p0 = 0.f, p1 = 0.f;
#pragma unroll
    for (int j = 0; j < 8; j++) {
        int c = 8 * j + cbase;
        float A0 = SAL[c],   B0 = SBE[c],   W0 = SWO[c];
        float A1 = SAL[c+1], B1 = SBE[c+1], W1 = SWO[c+1];
        p0 += fmaxf(d[j][0] * A0 + B0, 0.f) * W0
            + fmaxf(d[j][1] * A1 + B1, 0.f) * W1;
        p1 += fmaxf(d[j][2] * A0 + B0, 0.f) * W0
            + fmaxf(d[j][3] * A1 + B1, 0.f) * W1;
    }
    p0 += __shfl_xor_sync(0xFFFFFFFFu, p0, 1);
    p0 += __shfl_xor_sync(0xFFFFFFFFu, p0, 2);
    p1 += __shfl_xor_sync(0xFFFFFFFFu, p1, 1);
    p1 += __shfl_xor_sync(0xFFFFFFFFu, p1, 2);
    if ((lane & 3) == 0) {
        float bb = __ldg(&blin[0]);
        int n1 = nb + m0 + r0;
        int n2 = n1 + 8;
        if (n1 < NN) out[n1] = p0 + bb;
        if (n2 < NN) out[n2] = p1 + bb;
    }
}

// ============================================================================
// Launch — 5 kernels
// ============================================================================
extern "C" void kernel_launch(void* const* d_in, const int* in_sizes, int n_in,
                              void* d_out, int out_size) {
    const float* x   = (const float*)d_in[0];
    const int*   ei  = (const int*)d_in[1];   // int32 (jax x64 disabled)
    const int*   src = ei;
    const int*   dst = ei + EE;
    const float* W1l  = (const float*)d_in[2];
    const float* b1l  = (const float*)d_in[3];
    const float* W1r  = (const float*)d_in[4];
    const float* bn1g = (const float*)d_in[5];
    const float* bn1b = (const float*)d_in[6];
    const float* bn1m = (const float*)d_in[7];
    const float* bn1v = (const float*)d_in[8];
    const float* W2l  = (const float*)d_in[9];
    const float* b2l  = (const float*)d_in[10];
    const float* W2r  = (const float*)d_in[11];
    const float* bn2g = (const float*)d_in[12];
    const float* bn2b = (const float*)d_in[13];
    const float* bn2m = (const float*)d_in[14];
    const float* bn2v = (const float*)d_in[15];
    const float* Wlin = (const float*)d_in[16];
    const float* blin = (const float*)d_in[17];
    float* out = (float*)d_out;

    cudaFuncSetAttribute(k_layer1, cudaFuncAttributeMaxDynamicSharedMemorySize, L1_SMEM);
    cudaFuncSetAttribute(k_layer2, cudaFuncAttributeMaxDynamicSharedMemorySize, L2_SMEM);

    int nblk  = (NN + 127) / 128;            // 391
    int a1blk = (NN * 8 + 255) / 256;        // 1563  (4 nodes/warp)
    int a2blk = (NN * 8 + 255) / 256;        // 1563  (4 nodes/warp)

    k_fill<<<(EE / 4 + 255) / 256, 256>>>(src, dst);
    k_agg1<<<a1blk, 256>>>(x);
    k_layer1<<<nblk, 256, L1_SMEM>>>(x, W1l, b1l, W1r, bn1g, bn1b, bn1m, bn1v);
    k_agg2<<<a2blk, 256>>>();
    k_layer2<<<nblk, 256, L2_SMEM>>>(W2l, b2l, W2r, bn2g, bn2b, bn2m, bn2v,
                                     Wlin, blin, out);
}

// round 14
// speedup vs baseline: 1.9552x; 1.2209x over previous
#include <cuda_runtime.h>
#include <cuda_fp16.h>

#define NN   50000
#define EE   800000
#define INC  32
#define HIDC 64
#define MAXDEG 96

// -------------------- device scratch (no allocation allowed) ----------------
// Invariant: g_cnt is ZERO at entry of every kernel_launch call
// (zeroed at module load; restored by k_agg2 each call).
__device__ __align__(16) int    g_cnt[NN];            // degree + fill cursor
__device__ __align__(16) int    g_csrp[NN * MAXDEG];  // padded CSR: src by dst
__device__ __align__(16) __half g_agg1h[NN * INC];    // normalized mean of x (fp16)
__device__ __align__(16) __half g_agg2h[NN * HIDC];   // normalized mean of h (fp16)
__device__ __align__(16) __half g_h[NN * HIDC];       // layer-1 output (fp16)

// -------------------- tensor-core helpers ------------------------------------
__device__ __forceinline__ void ldsm_x4(unsigned* r, unsigned addr) {
    asm volatile("ldmatrix.sync.aligned.m8n8.x4.shared.b16 {%0,%1,%2,%3}, [%4];"
                 : "=r"(r[0]), "=r"(r[1]), "=r"(r[2]), "=r"(r[3]) : "r"(addr));
}
__device__ __forceinline__ void ldsm_x2t(unsigned& r0, unsigned& r1, unsigned addr) {
    asm volatile("ldmatrix.sync.aligned.m8n8.x2.trans.shared.b16 {%0,%1}, [%2];"
                 : "=r"(r0), "=r"(r1) : "r"(addr));
}
__device__ __forceinline__ void mma16816(float* d, const unsigned* a,
                                         unsigned b0, unsigned b1) {
    asm volatile("mma.sync.aligned.m16n8k16.row.col.f32.f16.f16.f32 "
                 "{%0,%1,%2,%3}, {%4,%5,%6,%7}, {%8,%9}, {%0,%1,%2,%3};"
                 : "+f"(d[0]), "+f"(d[1]), "+f"(d[2]), "+f"(d[3])
                 : "r"(a[0]), "r"(a[1]), "r"(a[2]), "r"(a[3]), "r"(b0), "r"(b1));
}

// ============================================================================
// Padded-CSR fill: 4 edges per thread (int4 loads, 4 independent atomic chains)
// ============================================================================
__global__ __launch_bounds__(256)
void k_fill(const int* __restrict__ src, const int* __restrict__ dst) {
    int q = blockIdx.x * blockDim.x + threadIdx.x;   // quad id
    if (q >= EE / 4) return;
    int4 s4 = __ldg((const int4*)src + q);
    int4 d4 = __ldg((const int4*)dst + q);
    int sl0 = atomicAdd(&g_cnt[d4.x], 1);
    int sl1 = atomicAdd(&g_cnt[d4.y], 1);
    int sl2 = atomicAdd(&g_cnt[d4.z], 1);
    int sl3 = atomicAdd(&g_cnt[d4.w], 1);
    if (sl0 < MAXDEG) g_csrp[d4.x * MAXDEG + sl0] = s4.x;
    if (sl1 < MAXDEG) g_csrp[d4.y * MAXDEG + sl1] = s4.y;
    if (sl2 < MAXDEG) g_csrp[d4.z * MAXDEG + sl2] = s4.z;
    if (sl3 < MAXDEG) g_csrp[d4.w * MAXDEG + sl3] = s4.w;
}

// ============================================================================
// Agg 1: 4 nodes per warp; 8 lanes x float4 cover the 32 channels. fp16 out.
// ============================================================================
__global__ __launch_bounds__(256)
void k_agg1(const float* __restrict__ x) {
    int gt   = blockIdx.x * blockDim.x + threadIdx.x;
    int wid  = gt >> 5;
    int lane = gt & 31;
    int sub  = lane >> 3;        // node within warp (0..3)
    int c4   = lane & 7;         // float4 channel group (0..7)
    int n = wid * 4 + sub;
    if (n >= NN) return;

    int deg  = g_cnt[n];
    int degc = deg < MAXDEG ? deg : MAXDEG;
    const int*    row = &g_csrp[n * MAXDEG];
    const float4* xp  = (const float4*)x;

    float4 acc = make_float4(0.f, 0.f, 0.f, 0.f);
    int j = 0;
    for (; j + 3 < degc; j += 4) {
        int4 s = __ldg((const int4*)(row + j));
        float4 v0 = __ldg(xp + (s.x * 8 + c4));
        float4 v1 = __ldg(xp + (s.y * 8 + c4));
        float4 v2 = __ldg(xp + (s.z * 8 + c4));
        float4 v3 = __ldg(xp + (s.w * 8 + c4));
        acc.x += (v0.x + v1.x) + (v2.x + v3.x);
        acc.y += (v0.y + v1.y) + (v2.y + v3.y);
        acc.z += (v0.z + v1.z) + (v2.z + v3.z);
        acc.w += (v0.w + v1.w) + (v2.w + v3.w);
    }
    for (; j < degc; j++) {
        float4 v = __ldg(xp + (__ldg(row + j) * 8 + c4));
        acc.x += v.x; acc.y += v.y; acc.z += v.z; acc.w += v.w;
    }
    float dinv = 1.0f / fmaxf((float)deg, 1.0f);
    __half2 h0 = __floats2half2_rn(acc.x * dinv, acc.y * dinv);
    __half2 h1 = __floats2half2_rn(acc.z * dinv, acc.w * dinv);
    uint2 p;
    p.x = *(unsigned int*)&h0;
    p.y = *(unsigned int*)&h1;
    ((uint2*)g_agg1h)[n * 8 + c4] = p;
}

// ============================================================================
// Agg 2: 4 nodes per warp; 8 lanes x uint4 (8 fp16) cover the 64 channels.
// fp16 output. Also restores g_cnt[n] = 0 (last reader of deg).
// ============================================================================
__global__ __launch_bounds__(256)
void k_agg2() {
    int gt   = blockIdx.x * blockDim.x + threadIdx.x;
    int wid  = gt >> 5;
    int lane = gt & 31;
    int sub  = lane >> 3;        // node within warp (0..3)
    int c8   = lane & 7;         // 8-halves group (0..7)
    int n = wid * 4 + sub;
    if (n >= NN) return;

    int deg  = g_cnt[n];
    int degc = deg < MAXDEG ? deg : MAXDEG;
    const int*   row = &g_csrp[n * MAXDEG];
    const uint4* hp  = (const uint4*)g_h;    // 8 halves per uint4

    float acc[8];
#pragma unroll
    for (int i = 0; i < 8; i++) acc[i] = 0.f;

    int j = 0;
    for (; j + 7 < degc; j += 8) {
        int4 sA = __ldg((const int4*)(row + j));
        int4 sB = __ldg((const int4*)(row + j + 4));
        uint4 u0 = __ldg(hp + (sA.x * 8 + c8));
        uint4 u1 = __ldg(hp + (sA.y * 8 + c8));
        uint4 u2 = __ldg(hp + (sA.z * 8 + c8));
        uint4 u3 = __ldg(hp + (sA.w * 8 + c8));
        uint4 u4 = __ldg(hp + (sB.x * 8 + c8));
        uint4 u5 = __ldg(hp + (sB.y * 8 + c8));
        uint4 u6 = __ldg(hp + (sB.z * 8 + c8));
        uint4 u7 = __ldg(hp + (sB.w * 8 + c8));
#pragma unroll
        for (int q = 0; q < 8; q++) {
            uint4 u = (q == 0) ? u0 : (q == 1) ? u1 : (q == 2) ? u2 :
                      (q == 3) ? u3 : (q == 4) ? u4 : (q == 5) ? u5 :
                      (q == 6) ? u6 : u7;
            float2 f0 = __half22float2(*(__half2*)&u.x);
            float2 f1 = __half22float2(*(__half2*)&u.y);
            float2 f2 = __half22float2(*(__half2*)&u.z);
            float2 f3 = __half22float2(*(__half2*)&u.w);
            acc[0] += f0.x; acc[1] += f0.y;
            acc[2] += f1.x; acc[3] += f1.y;
            acc[4] += f2.x; acc[5] += f2.y;
            acc[6] += f3.x; acc[7] += f3.y;
        }
    }
    for (; j + 3 < degc; j += 4) {
        int4 s = __ldg((const int4*)(row + j));
        uint4 u0 = __ldg(hp + (s.x * 8 + c8));
        uint4 u1 = __ldg(hp + (s.y * 8 + c8));
        uint4 u2 = __ldg(hp + (s.z * 8 + c8));
        uint4 u3 = __ldg(hp + (s.w * 8 + c8));
#pragma unroll
        for (int q = 0; q < 4; q++) {
            uint4 u = (q == 0) ? u0 : (q == 1) ? u1 : (q == 2) ? u2 : u3;
            float2 f0 = __half22float2(*(__half2*)&u.x);
            float2 f1 = __half22float2(*(__half2*)&u.y);
            float2 f2 = __half22float2(*(__half2*)&u.z);
            float2 f3 = __half22float2(*(__half2*)&u.w);
            acc[0] += f0.x; acc[1] += f0.y;
            acc[2] += f1.x; acc[3] += f1.y;
            acc[4] += f2.x; acc[5] += f2.y;
            acc[6] += f3.x; acc[7] += f3.y;
        }
    }
    for (; j < degc; j++) {
        uint4 u = __ldg(hp + (__ldg(row + j) * 8 + c8));
        float2 f0 = __half22float2(*(__half2*)&u.x);
        float2 f1 = __half22float2(*(__half2*)&u.y);
        float2 f2 = __half22float2(*(__half2*)&u.z);
        float2 f3 = __half22float2(*(__half2*)&u.w);
        acc[0] += f0.x; acc[1] += f0.y;
        acc[2] += f1.x; acc[3] += f1.y;
        acc[4] += f2.x; acc[5] += f2.y;
        acc[6] += f3.x; acc[7] += f3.y;
    }
    float dinv = 1.0f / fmaxf((float)deg, 1.0f);
    __half2 p0 = __floats2half2_rn(acc[0]*dinv, acc[1]*dinv);
    __half2 p1 = __floats2half2_rn(acc[2]*dinv, acc[3]*dinv);
    __half2 p2 = __floats2half2_rn(acc[4]*dinv, acc[5]*dinv);
    __half2 p3 = __floats2half2_rn(acc[6]*dinv, acc[7]*dinv);
    uint4 pkt;
    pkt.x = *(unsigned int*)&p0;
    pkt.y = *(unsigned int*)&p1;
    pkt.z = *(unsigned int*)&p2;
    pkt.w = *(unsigned int*)&p3;
    ((uint4*)g_agg2h)[n * 8 + c8] = pkt;
    if (c8 == 0) g_cnt[n] = 0;   // restore invariant
}

// ============================================================================
// Layer 1 via tensor cores (mma.sync m16n8k16, fp16 in, fp32 accum):
//   D[128x64] = A[128x64] @ Wcat[64x64];  A = [agg1h | x->fp16]
//   h[n][o] = relu(a1[o]*D[n][o] + b1[o])  stored fp16
// SA: fp16 [m][k], stride 72 halves; SB: fp16 [k][n], stride 72 halves.
// ============================================================================
#define L1_KH    72
#define L1_NH    72
#define L1_SA    0                            // 128*72*2 = 18432
#define L1_SB    18432                        // 64*72*2  = 9216
#define L1_ALPHA (18432 + 9216)               // 27648
#define L1_BETA  (L1_ALPHA + 256)
#define L1_SMEM  (L1_BETA + 256)              // 28160

__global__ __launch_bounds__(256)
void k_layer1(const float* __restrict__ x,
              const float* __restrict__ W1l, const float* __restrict__ b1l,
              const float* __restrict__ W1r,
              const float* __restrict__ g1, const float* __restrict__ bb1,
              const float* __restrict__ m1, const float* __restrict__ v1) {
    extern __shared__ char smem_raw[];
    __half* SA = (__half*)(smem_raw + L1_SA);
    __half* SB = (__half*)(smem_raw + L1_SB);
    float* SAL = (float*)(smem_raw + L1_ALPHA);
    float* SBE = (float*)(smem_raw + L1_BETA);

    int t = threadIdx.x;
    int nb = blockIdx.x * 128;
    int lane = t & 31, w = t >> 5;

    // Stage SA [m][k] fp16: k[0,32) = agg1h (direct copy), k[32,64) = x (cvt).
#pragma unroll
    for (int it = 0; it < 4; it++) {
        int f = t + 256 * it;            // uint4 id [0,1024): m = f>>3, g = f&7
        int m = f >> 3, g = f & 7;
        int n = nb + m; int nc = n < NN ? n : NN - 1;
        uint4 u;
        if (g < 4) {
            u = __ldg((const uint4*)g_agg1h + (nc * 4 + g));
        } else {
            float4 a = __ldg((const float4*)&x[(long long)nc * INC] + (g - 4) * 2);
            float4 b = __ldg((const float4*)&x[(long long)nc * INC] + (g - 4) * 2 + 1);
            __half2 h0 = __floats2half2_rn(a.x, a.y);
            __half2 h1 = __floats2half2_rn(a.z, a.w);
            __half2 h2 = __floats2half2_rn(b.x, b.y);
            __half2 h3 = __floats2half2_rn(b.z, b.w);
            u.x = *(unsigned int*)&h0;
            u.y = *(unsigned int*)&h1;
            u.z = *(unsigned int*)&h2;
            u.w = *(unsigned int*)&h3;
        }
        *(uint4*)&SA[m * L1_KH + g * 8] = u;
    }
    // Stage SB [k][n] fp16 from fp32 weights (k[0,32)=W1l, k[32,64)=W1r)
#pragma unroll
    for (int it = 0; it < 4; it++) {
        int f4 = t + 256 * it;           // float4 id [0,1024)
        int k = f4 >> 4, j = f4 & 15;
        float4 wv = (f4 < 512) ? __ldg((const float4*)W1l + f4)
                               : __ldg((const float4*)W1r + (f4 - 512));
        __half2 h01 = __floats2half2_rn(wv.x, wv.y);
        __half2 h23 = __floats2half2_rn(wv.z, wv.w);
        uint2 p;
        p.x = *(unsigned int*)&h01;
        p.y = *(unsigned int*)&h23;
        *(uint2*)&SB[k * L1_NH + j * 4] = p;
    }
    if (t < HIDC) {
        float a = g1[t] * rsqrtf(v1[t] + 1e-5f);
        SAL[t] = a;
        SBE[t] = (b1l[t] - m1[t]) * a + bb1[t];
    }
    __syncthreads();

    // MMA: warp w -> rows [16w, 16w+16), K=64 (4 steps)
    int m0 = w * 16;
    float d[8][4];
#pragma unroll
    for (int j = 0; j < 8; j++)
#pragma unroll
        for (int i = 0; i < 4; i++) d[j][i] = 0.f;

    int arow = m0 + (lane & 15);
    int akk  = (lane >> 4) * 8;
    int brow = lane & 15;

#pragma unroll
    for (int s = 0; s < 4; s++) {
        unsigned afr[4];
        unsigned aaddr = (unsigned)__cvta_generic_to_shared(
            &SA[arow * L1_KH + s * 16 + akk]);
        ldsm_x4(afr, aaddr);
#pragma unroll
        for (int j = 0; j < 8; j++) {
            unsigned b0, b1;
            unsigned baddr = (unsigned)__cvta_generic_to_shared(
                &SB[(s * 16 + brow) * L1_NH + j * 8]);
            ldsm_x2t(b0, b1, baddr);
            mma16816(d[j], afr, b0, b1);
        }
    }

    // Epilogue: BN + ReLU, store h fp16 directly from fragments.
    // Thread owns rows (m0+r0) and (m0+r0+8), cols 8j + cbase + {0,1}.
    int r0 = lane >> 2;
    int cbase = 2 * (lane & 3);
    int n1 = nb + m0 + r0;
    int n2 = n1 + 8;
#pragma unroll
    for (int j = 0; j < 8; j++) {
        int c = 8 * j + cbase;
        float A0 = SAL[c],   B0 = SBE[c];
        float A1 = SAL[c+1], B1 = SBE[c+1];
        if (n1 < NN) {
            __half2 hv = __floats2half2_rn(
                fmaxf(d[j][0] * A0 + B0, 0.f),
                fmaxf(d[j][1] * A1 + B1, 0.f));
            *(__half2*)&g_h[(long long)n1 * HIDC + c] = hv;
        }
        if (n2 < NN) {
            __half2 hv = __floats2half2_rn(
                fmaxf(d[j][2] * A0 + B0, 0.f),
                fmaxf(d[j][3] * A1 + B1, 0.f));
            *(__half2*)&g_h[(long long)n2 * HIDC + c] = hv;
        }
    }
}

// ============================================================================
// Layer 2 + head via tensor cores (identical to R13 measured version)
// ============================================================================
#define L2_KH    136                          // SA row stride (halves)
#define L2_NH    72                           // SB row stride (halves)
#define L2_SA    0                            // 128*136*2 = 34816
#define L2_SB    34816                        // 128*72*2  = 18432
#define L2_ALPHA (34816 + 18432)              // 53248
#define L2_BETA  (L2_ALPHA + 256)
#define L2_SWO   (L2_BETA + 256)
#define L2_SMEM  (L2_SWO + 256)               // 54016

__global__ __launch_bounds__(256)
void k_layer2(const float* __restrict__ W2l, const float* __restrict__ b2l,
              const float* __restrict__ W2r,
              const float* __restrict__ g2, const float* __restrict__ bb2,
              const float* __restrict__ m2, const float* __restrict__ v2,
              const float* __restrict__ Wlin, const float* __restrict__ blin,
              float* __restrict__ out) {
    extern __shared__ char smem_raw[];
    __half* SA = (__half*)(smem_raw + L2_SA);
    __half* SB = (__half*)(smem_raw + L2_SB);
    float* SAL = (float*)(smem_raw + L2_ALPHA);
    float* SBE = (float*)(smem_raw + L2_BETA);
    float* SWO = (float*)(smem_raw + L2_SWO);

    int t = threadIdx.x;
    int nb = blockIdx.x * 128;
    int lane = t & 31, w = t >> 5;

    // Stage SA [m][k] fp16: k[0,64) = agg2h, k[64,128) = h. Direct uint4 copy.
#pragma unroll
    for (int it = 0; it < 8; it++) {
        int f = t + 256 * it;            // uint4 id [0,2048)
        int m = f >> 4, g = f & 15;
        int n = nb + m; int nc = n < NN ? n : NN - 1;
        uint4 u = (g < 8) ? __ldg((const uint4*)g_agg2h + (nc * 8 + g))
                          : __ldg((const uint4*)g_h + (nc * 8 + (g - 8)));
        *(uint4*)&SA[m * L2_KH + g * 8] = u;
    }
    // Stage SB [k][n] fp16 from fp32 weights (layout already [k][n])
#pragma unroll
    for (int it = 0; it < 8; it++) {
        int f4 = t + 256 * it;           // float4 id [0,2048)
        int k = f4 >> 4, j = f4 & 15;
        float4 wv = (f4 < 1024) ? __ldg((const float4*)W2l + f4)
                                : __ldg((const float4*)W2r + (f4 - 1024));
        __half2 h01 = __floats2half2_rn(wv.x, wv.y);
        __half2 h23 = __floats2half2_rn(wv.z, wv.w);
        uint2 p;
        p.x = *(unsigned int*)&h01;
        p.y = *(unsigned int*)&h23;
        *(uint2*)&SB[k * L2_NH + j * 4] = p;
    }
    if (t < HIDC) {
        float a = g2[t] * rsqrtf(v2[t] + 1e-5f);
        SAL[t] = a;
        SBE[t] = (b2l[t] - m2[t]) * a + bb2[t];
        SWO[t] = Wlin[t];
    }
    __syncthreads();

    // MMA: warp w -> rows [16w, 16w+16)
    int m0 = w * 16;
    float d[8][4];
#pragma unroll
    for (int j = 0; j < 8; j++)
#pragma unroll
        for (int i = 0; i < 4; i++) d[j][i] = 0.f;

    int arow = m0 + (lane & 15);
    int akk  = (lane >> 4) * 8;
    int brow = lane & 15;

#pragma unroll
    for (int s = 0; s < 8; s++) {
        unsigned afr[4];
        unsigned aaddr = (unsigned)__cvta_generic_to_shared(
            &SA[arow * L2_KH + s * 16 + akk]);
        ldsm_x4(afr, aaddr);
#pragma unroll
        for (int j = 0; j < 8; j++) {
            unsigned b0, b1;
            unsigned baddr = (unsigned)__cvta_generic_to_shared(
                &SB[(s * 16 + brow) * L2_NH + j * 8]);
            ldsm_x2t(b0, b1, baddr);
            mma16816(d[j], afr, b0, b1);
        }
    }

    // Epilogue: BN + ReLU + head dot on D fragments.
    int r0 = lane >> 2;
    int cbase = 2 * (lane & 3);
    float p0 = 0.f, p1 = 0.f;
#pragma unroll
    for (int j = 0; j < 8; j++) {
        int c = 8 * j + cbase;
        float A0 = SAL[c],   B0 = SBE[c],   W0 = SWO[c];
        float A1 = SAL[c+1], B1 = SBE[c+1], W1 = SWO[c+1];
        p0 += fmaxf(d[j][0] * A0 + B0, 0.f) * W0
            + fmaxf(d[j][1] * A1 + B1, 0.f) * W1;
        p1 += fmaxf(d[j][2] * A0 + B0, 0.f) * W0
            + fmaxf(d[j][3] * A1 + B1, 0.f) * W1;
    }
    p0 += __shfl_xor_sync(0xFFFFFFFFu, p0, 1);
    p0 += __shfl_xor_sync(0xFFFFFFFFu, p0, 2);
    p1 += __shfl_xor_sync(0xFFFFFFFFu, p1, 1);
    p1 += __shfl_xor_sync(0xFFFFFFFFu, p1, 2);
    if ((lane & 3) == 0) {
        float bb = __ldg(&blin[0]);
        int n1 = nb + m0 + r0;
        int n2 = n1 + 8;
        if (n1 < NN) out[n1] = p0 + bb;
        if (n2 < NN) out[n2] = p1 + bb;
    }
}

// ============================================================================
// Launch — 5 kernels
// ============================================================================
extern "C" void kernel_launch(void* const* d_in, const int* in_sizes, int n_in,
                              void* d_out, int out_size) {
    const float* x   = (const float*)d_in[0];
    const int*   ei  = (const int*)d_in[1];   // int32 (jax x64 disabled)
    const int*   src = ei;
    const int*   dst = ei + EE;
    const float* W1l  = (const float*)d_in[2];
    const float* b1l  = (const float*)d_in[3];
    const float* W1r  = (const float*)d_in[4];
    const float* bn1g = (const float*)d_in[5];
    const float* bn1b = (const float*)d_in[6];
    const float* bn1m = (const float*)d_in[7];
    const float* bn1v = (const float*)d_in[8];
    const float* W2l  = (const float*)d_in[9];
    const float* b2l  = (const float*)d_in[10];
    const float* W2r  = (const float*)d_in[11];
    const float* bn2g = (const float*)d_in[12];
    const float* bn2b = (const float*)d_in[13];
    const float* bn2m = (const float*)d_in[14];
    const float* bn2v = (const float*)d_in[15];
    const float* Wlin = (const float*)d_in[16];
    const float* blin = (const float*)d_in[17];
    float* out = (float*)d_out;

    cudaFuncSetAttribute(k_layer1, cudaFuncAttributeMaxDynamicSharedMemorySize, L1_SMEM);
    cudaFuncSetAttribute(k_layer2, cudaFuncAttributeMaxDynamicSharedMemorySize, L2_SMEM);

    int nblk  = (NN + 127) / 128;            // 391
    int a1blk = (NN * 8 + 255) / 256;        // 1563  (4 nodes/warp)
    int a2blk = (NN * 8 + 255) / 256;        // 1563  (4 nodes/warp)

    k_fill<<<(EE / 4 + 255) / 256, 256>>>(src, dst);
    k_agg1<<<a1blk, 256>>>(x);
    k_layer1<<<nblk, 256, L1_SMEM>>>(x, W1l, b1l, W1r, bn1g, bn1b, bn1m, bn1v);
    k_agg2<<<a2blk, 256>>>();
    k_layer2<<<nblk, 256, L2_SMEM>>>(W2l, b2l, W2r, bn2g, bn2b, bn2m, bn2v,
                                     Wlin, blin, out);
}

// round 15
// speedup vs baseline: 2.0071x; 1.0265x over previous
#include <cuda_runtime.h>
#include <cuda_fp16.h>

#define NN   50000
#define EE   800000
#define INC  32
#define HIDC 64
#define MAXDEG 96

// -------------------- device scratch (no allocation allowed) ----------------
// Invariant: g_cnt is ZERO at entry of every kernel_launch call
// (zeroed at module load; restored by k_agg2 each call).
__device__ __align__(16) int    g_cnt[NN];            // degree + fill cursor
__device__ __align__(16) int    g_csrp[NN * MAXDEG];  // padded CSR: src by dst
__device__ __align__(16) __half g_xh[NN * INC];       // x in fp16
__device__ __align__(16) __half g_agg1h[NN * INC];    // normalized mean of x (fp16)
__device__ __align__(16) __half g_agg2h[NN * HIDC];   // normalized mean of h (fp16)
__device__ __align__(16) __half g_h[NN * HIDC];       // layer-1 output (fp16)

// -------------------- packed math helpers -----------------------------------
__device__ __forceinline__ unsigned long long pack2(float lo, float hi) {
    unsigned long long r;
    asm("mov.b64 %0, {%1, %2};" : "=l"(r) : "f"(lo), "f"(hi));
    return r;
}
__device__ __forceinline__ void unpack2(float& lo, float& hi, unsigned long long v) {
    asm("mov.b64 {%0, %1}, %2;" : "=f"(lo), "=f"(hi) : "l"(v));
}
#define ADD2(d, a) asm("add.rn.f32x2 %0, %0, %1;" : "+l"(d) : "l"(a))

// -------------------- tensor-core helpers ------------------------------------
__device__ __forceinline__ void ldsm_x4(unsigned* r, unsigned addr) {
    asm volatile("ldmatrix.sync.aligned.m8n8.x4.shared.b16 {%0,%1,%2,%3}, [%4];"
                 : "=r"(r[0]), "=r"(r[1]), "=r"(r[2]), "=r"(r[3]) : "r"(addr));
}
__device__ __forceinline__ void ldsm_x2t(unsigned& r0, unsigned& r1, unsigned addr) {
    asm volatile("ldmatrix.sync.aligned.m8n8.x2.trans.shared.b16 {%0,%1}, [%2];"
                 : "=r"(r0), "=r"(r1) : "r"(addr));
}
__device__ __forceinline__ void mma16816(float* d, const unsigned* a,
                                         unsigned b0, unsigned b1) {
    asm volatile("mma.sync.aligned.m16n8k16.row.col.f32.f16.f16.f32 "
                 "{%0,%1,%2,%3}, {%4,%5,%6,%7}, {%8,%9}, {%0,%1,%2,%3};"
                 : "+f"(d[0]), "+f"(d[1]), "+f"(d[2]), "+f"(d[3])
                 : "r"(a[0]), "r"(a[1]), "r"(a[2]), "r"(a[3]), "r"(b0), "r"(b1));
}

// ============================================================================
// Fill + x->fp16 convert in one grid.
// Threads [0, EE/4): padded-CSR fill (4 edges each, int4 loads).
// Threads [EE/4, EE/4 + NN*INC/8): convert 8 floats of x to fp16.
// ============================================================================
#define FILL_T   (EE / 4)                    // 200000
#define XCVT_T   (NN * INC / 8)              // 200000

__global__ __launch_bounds__(256)
void k_fill(const int* __restrict__ src, const int* __restrict__ dst,
            const float* __restrict__ x) {
    int q = blockIdx.x * blockDim.x + threadIdx.x;
    if (q < FILL_T) {
        int4 s4 = __ldg((const int4*)src + q);
        int4 d4 = __ldg((const int4*)dst + q);
        int sl0 = atomicAdd(&g_cnt[d4.x], 1);
        int sl1 = atomicAdd(&g_cnt[d4.y], 1);
        int sl2 = atomicAdd(&g_cnt[d4.z], 1);
        int sl3 = atomicAdd(&g_cnt[d4.w], 1);
        if (sl0 < MAXDEG) g_csrp[d4.x * MAXDEG + sl0] = s4.x;
        if (sl1 < MAXDEG) g_csrp[d4.y * MAXDEG + sl1] = s4.y;
        if (sl2 < MAXDEG) g_csrp[d4.z * MAXDEG + sl2] = s4.z;
        if (sl3 < MAXDEG) g_csrp[d4.w * MAXDEG + sl3] = s4.w;
    } else if (q < FILL_T + XCVT_T) {
        int i = q - FILL_T;                  // 8-float chunk id
        float4 a = __ldg((const float4*)x + 2 * i);
        float4 b = __ldg((const float4*)x + 2 * i + 1);
        __half2 h0 = __floats2half2_rn(a.x, a.y);
        __half2 h1 = __floats2half2_rn(a.z, a.w);
        __half2 h2 = __floats2half2_rn(b.x, b.y);
        __half2 h3 = __floats2half2_rn(b.z, b.w);
        uint4 u;
        u.x = *(unsigned int*)&h0;
        u.y = *(unsigned int*)&h1;
        u.z = *(unsigned int*)&h2;
        u.w = *(unsigned int*)&h3;
        ((uint4*)g_xh)[i] = u;
    }
}

// ============================================================================
// Agg 1: 8 nodes per warp; 4 lanes x uint4 (8 fp16) cover the 32 channels.
// Gathers 64B fp16 rows. fp16 output. f32 accumulation (packed adds).
// ============================================================================
__global__ __launch_bounds__(256)
void k_agg1() {
    int gt   = blockIdx.x * blockDim.x + threadIdx.x;
    int wid  = gt >> 5;
    int lane = gt & 31;
    int sub  = lane >> 2;        // node within warp (0..7)
    int c4   = lane & 3;         // uint4 group (0..3)
    int n = wid * 8 + sub;
    if (n >= NN) return;

    int deg  = g_cnt[n];
    int degc = deg < MAXDEG ? deg : MAXDEG;
    const int*   row = &g_csrp[n * MAXDEG];
    const uint4* xp  = (const uint4*)g_xh;   // 4 uint4 per row

    unsigned long long ac[4];
#pragma unroll
    for (int i = 0; i < 4; i++) ac[i] = 0ull;

    int j = 0;
    for (; j + 7 < degc; j += 8) {
        int4 sA = __ldg((const int4*)(row + j));
        int4 sB = __ldg((const int4*)(row + j + 4));
        uint4 u0 = __ldg(xp + (sA.x * 4 + c4));
        uint4 u1 = __ldg(xp + (sA.y * 4 + c4));
        uint4 u2 = __ldg(xp + (sA.z * 4 + c4));
        uint4 u3 = __ldg(xp + (sA.w * 4 + c4));
        uint4 u4 = __ldg(xp + (sB.x * 4 + c4));
        uint4 u5 = __ldg(xp + (sB.y * 4 + c4));
        uint4 u6 = __ldg(xp + (sB.z * 4 + c4));
        uint4 u7 = __ldg(xp + (sB.w * 4 + c4));
#pragma unroll
        for (int q = 0; q < 8; q++) {
            uint4 u = (q == 0) ? u0 : (q == 1) ? u1 : (q == 2) ? u2 :
                      (q == 3) ? u3 : (q == 4) ? u4 : (q == 5) ? u5 :
                      (q == 6) ? u6 : u7;
            float2 f0 = __half22float2(*(__half2*)&u.x);
            float2 f1 = __half22float2(*(__half2*)&u.y);
            float2 f2 = __half22float2(*(__half2*)&u.z);
            float2 f3 = __half22float2(*(__half2*)&u.w);
            ADD2(ac[0], pack2(f0.x, f0.y));
            ADD2(ac[1], pack2(f1.x, f1.y));
            ADD2(ac[2], pack2(f2.x, f2.y));
            ADD2(ac[3], pack2(f3.x, f3.y));
        }
    }
    for (; j < degc; j++) {
        uint4 u = __ldg(xp + (__ldg(row + j) * 4 + c4));
        float2 f0 = __half22float2(*(__half2*)&u.x);
        float2 f1 = __half22float2(*(__half2*)&u.y);
        float2 f2 = __half22float2(*(__half2*)&u.z);
        float2 f3 = __half22float2(*(__half2*)&u.w);
        ADD2(ac[0], pack2(f0.x, f0.y));
        ADD2(ac[1], pack2(f1.x, f1.y));
        ADD2(ac[2], pack2(f2.x, f2.y));
        ADD2(ac[3], pack2(f3.x, f3.y));
    }
    float dinv = 1.0f / fmaxf((float)deg, 1.0f);
    float lo, hi;
    uint4 pkt;
    unpack2(lo, hi, ac[0]);
    __half2 h0 = __floats2half2_rn(lo * dinv, hi * dinv);
    pkt.x = *(unsigned int*)&h0;
    unpack2(lo, hi, ac[1]);
    __half2 h1 = __floats2half2_rn(lo * dinv, hi * dinv);
    pkt.y = *(unsigned int*)&h1;
    unpack2(lo, hi, ac[2]);
    __half2 h2 = __floats2half2_rn(lo * dinv, hi * dinv);
    pkt.z = *(unsigned int*)&h2;
    unpack2(lo, hi, ac[3]);
    __half2 h3 = __floats2half2_rn(lo * dinv, hi * dinv);
    pkt.w = *(unsigned int*)&h3;
    ((uint4*)g_agg1h)[n * 4 + c4] = pkt;
}

// ============================================================================
// Agg 2: 4 nodes per warp; 8 lanes x uint4 (8 fp16) cover the 64 channels.
// f32x2 packed accumulation. fp16 output. Restores g_cnt[n] = 0.
// ============================================================================
__global__ __launch_bounds__(256)
void k_agg2() {
    int gt   = blockIdx.x * blockDim.x + threadIdx.x;
    int wid  = gt >> 5;
    int lane = gt & 31;
    int sub  = lane >> 3;        // node within warp (0..3)
    int c8   = lane & 7;         // 8-halves group (0..7)
    int n = wid * 4 + sub;
    if (n >= NN) return;

    int deg  = g_cnt[n];
    int degc = deg < MAXDEG ? deg : MAXDEG;
    const int*   row = &g_csrp[n * MAXDEG];
    const uint4* hp  = (const uint4*)g_h;    // 8 halves per uint4

    unsigned long long ac[4];
#pragma unroll
    for (int i = 0; i < 4; i++) ac[i] = 0ull;

    int j = 0;
    for (; j + 7 < degc; j += 8) {
        int4 sA = __ldg((const int4*)(row + j));
        int4 sB = __ldg((const int4*)(row + j + 4));
        uint4 u0 = __ldg(hp + (sA.x * 8 + c8));
        uint4 u1 = __ldg(hp + (sA.y * 8 + c8));
        uint4 u2 = __ldg(hp + (sA.z * 8 + c8));
        uint4 u3 = __ldg(hp + (sA.w * 8 + c8));
        uint4 u4 = __ldg(hp + (sB.x * 8 + c8));
        uint4 u5 = __ldg(hp + (sB.y * 8 + c8));
        uint4 u6 = __ldg(hp + (sB.z * 8 + c8));
        uint4 u7 = __ldg(hp + (sB.w * 8 + c8));
#pragma unroll
        for (int q = 0; q < 8; q++) {
            uint4 u = (q == 0) ? u0 : (q == 1) ? u1 : (q == 2) ? u2 :
                      (q == 3) ? u3 : (q == 4) ? u4 : (q == 5) ? u5 :
                      (q == 6) ? u6 : u7;
            float2 f0 = __half22float2(*(__half2*)&u.x);
            float2 f1 = __half22float2(*(__half2*)&u.y);
            float2 f2 = __half22float2(*(__half2*)&u.z);
            float2 f3 = __half22float2(*(__half2*)&u.w);
            ADD2(ac[0], pack2(f0.x, f0.y));
            ADD2(ac[1], pack2(f1.x, f1.y));
            ADD2(ac[2], pack2(f2.x, f2.y));
            ADD2(ac[3], pack2(f3.x, f3.y));
        }
    }
    for (; j < degc; j++) {
        uint4 u = __ldg(hp + (__ldg(row + j) * 8 + c8));
        float2 f0 = __half22float2(*(__half2*)&u.x);
        float2 f1 = __half22float2(*(__half2*)&u.y);
        float2 f2 = __half22float2(*(__half2*)&u.z);
        float2 f3 = __half22float2(*(__half2*)&u.w);
        ADD2(ac[0], pack2(f0.x, f0.y));
        ADD2(ac[1], pack2(f1.x, f1.y));
        ADD2(ac[2], pack2(f2.x, f2.y));
        ADD2(ac[3], pack2(f3.x, f3.y));
    }
    float dinv = 1.0f / fmaxf((float)deg, 1.0f);
    float lo, hi;
    uint4 pkt;
    unpack2(lo, hi, ac[0]);
    __half2 p0 = __floats2half2_rn(lo * dinv, hi * dinv);
    pkt.x = *(unsigned int*)&p0;
    unpack2(lo, hi, ac[1]);
    __half2 p1 = __floats2half2_rn(lo * dinv, hi * dinv);
    pkt.y = *(unsigned int*)&p1;
    unpack2(lo, hi, ac[2]);
    __half2 p2 = __floats2half2_rn(lo * dinv, hi * dinv);
    pkt.z = *(unsigned int*)&p2;
    unpack2(lo, hi, ac[3]);
    __half2 p3 = __floats2half2_rn(lo * dinv, hi * dinv);
    pkt.w = *(unsigned int*)&p3;
    ((uint4*)g_agg2h)[n * 8 + c8] = pkt;
    if (c8 == 0) g_cnt[n] = 0;   // restore invariant
}

// ============================================================================
// Layer 1 via tensor cores: D[128x64] = [agg1h | xh] @ [W1l;W1r]
//   h[n][o] = relu(a1[o]*D[n][o] + b1[o])  stored fp16
// ============================================================================
#define L1_KH    72
#define L1_NH    72
#define L1_SA    0                            // 128*72*2 = 18432
#define L1_SB    18432                        // 64*72*2  = 9216
#define L1_ALPHA (18432 + 9216)               // 27648
#define L1_BETA  (L1_ALPHA + 256)
#define L1_SMEM  (L1_BETA + 256)              // 28160

__global__ __launch_bounds__(256)
void k_layer1(const float* __restrict__ W1l, const float* __restrict__ b1l,
              const float* __restrict__ W1r,
              const float* __restrict__ g1, const float* __restrict__ bb1,
              const float* __restrict__ m1, const float* __restrict__ v1) {
    extern __shared__ char smem_raw[];
    __half* SA = (__half*)(smem_raw + L1_SA);
    __half* SB = (__half*)(smem_raw + L1_SB);
    float* SAL = (float*)(smem_raw + L1_ALPHA);
    float* SBE = (float*)(smem_raw + L1_BETA);

    int t = threadIdx.x;
    int nb = blockIdx.x * 128;
    int lane = t & 31, w = t >> 5;

    // Stage SA [m][k] fp16: k[0,32) = agg1h, k[32,64) = xh. Direct uint4 copy.
#pragma unroll
    for (int it = 0; it < 4; it++) {
        int f = t + 256 * it;            // uint4 id [0,1024): m = f>>3, g = f&7
        int m = f >> 3, g = f & 7;
        int n = nb + m; int nc = n < NN ? n : NN - 1;
        uint4 u = (g < 4) ? __ldg((const uint4*)g_agg1h + (nc * 4 + g))
                          : __ldg((const uint4*)g_xh + (nc * 4 + (g - 4)));
        *(uint4*)&SA[m * L1_KH + g * 8] = u;
    }
    // Stage SB [k][n] fp16 from fp32 weights (k[0,32)=W1l, k[32,64)=W1r)
#pragma unroll
    for (int it = 0; it < 4; it++) {
        int f4 = t + 256 * it;           // float4 id [0,1024)
        int k = f4 >> 4, j = f4 & 15;
        float4 wv = (f4 < 512) ? __ldg((const float4*)W1l + f4)
                               : __ldg((const float4*)W1r + (f4 - 512));
        __half2 h01 = __floats2half2_rn(wv.x, wv.y);
        __half2 h23 = __floats2half2_rn(wv.z, wv.w);
        uint2 p;
        p.x = *(unsigned int*)&h01;
        p.y = *(unsigned int*)&h23;
        *(uint2*)&SB[k * L1_NH + j * 4] = p;
    }
    if (t < HIDC) {
        float a = g1[t] * rsqrtf(v1[t] + 1e-5f);
        SAL[t] = a;
        SBE[t] = (b1l[t] - m1[t]) * a + bb1[t];
    }
    __syncthreads();

    // MMA: warp w -> rows [16w, 16w+16), K=64 (4 steps)
    int m0 = w * 16;
    float d[8][4];
#pragma unroll
    for (int j = 0; j < 8; j++)
#pragma unroll
        for (int i = 0; i < 4; i++) d[j][i] = 0.f;

    int arow = m0 + (lane & 15);
    int akk  = (lane >> 4) * 8;
    int brow = lane & 15;

#pragma unroll
    for (int s = 0; s < 4; s++) {
        unsigned afr[4];
        unsigned aaddr = (unsigned)__cvta_generic_to_shared(
            &SA[arow * L1_KH + s * 16 + akk]);
        ldsm_x4(afr, aaddr);
#pragma unroll
        for (int j = 0; j < 8; j++) {
            unsigned b0, b1;
            unsigned baddr = (unsigned)__cvta_generic_to_shared(
                &SB[(s * 16 + brow) * L1_NH + j * 8]);
            ldsm_x2t(b0, b1, baddr);
            mma16816(d[j], afr, b0, b1);
        }
    }

    // Epilogue: BN + ReLU, store h fp16 directly from fragments.
    int r0 = lane >> 2;
    int cbase = 2 * (lane & 3);
    int n1 = nb + m0 + r0;
    int n2 = n1 + 8;
#pragma unroll
    for (int j = 0; j < 8; j++) {
        int c = 8 * j + cbase;
        float A0 = SAL[c],   B0 = SBE[c];
        float A1 = SAL[c+1], B1 = SBE[c+1];
        if (n1 < NN) {
            __half2 hv = __floats2half2_rn(
                fmaxf(d[j][0] * A0 + B0, 0.f),
                fmaxf(d[j][1] * A1 + B1, 0.f));
            *(__half2*)&g_h[(long long)n1 * HIDC + c] = hv;
        }
        if (n2 < NN) {
            __half2 hv = __floats2half2_rn(
                fmaxf(d[j][2] * A0 + B0, 0.f),
                fmaxf(d[j][3] * A1 + B1, 0.f));
            *(__half2*)&g_h[(long long)n2 * HIDC + c] = hv;
        }
    }
}

// ============================================================================
// Layer 2 + head via tensor cores (identical to R13/R14 measured version)
// ============================================================================
#define L2_KH    136                          // SA row stride (halves)
#define L2_NH    72                           // SB row stride (halves)
#define L2_SA    0                            // 128*136*2 = 34816
#define L2_SB    34816                        // 128*72*2  = 18432
#define L2_ALPHA (34816 + 18432)              // 53248
#define L2_BETA  (L2_ALPHA + 256)
#define L2_SWO   (L2_BETA + 256)
#define L2_SMEM  (L2_SWO + 256)               // 54016

__global__ __launch_bounds__(256)
void k_layer2(const float* __restrict__ W2l, const float* __restrict__ b2l,
              const float* __restrict__ W2r,
              const float* __restrict__ g2, const float* __restrict__ bb2,
              const float* __restrict__ m2, const float* __restrict__ v2,
              const float* __restrict__ Wlin, const float* __restrict__ blin,
              float* __restrict__ out) {
    extern __shared__ char smem_raw[];
    __half* SA = (__half*)(smem_raw + L2_SA);
    __half* SB = (__half*)(smem_raw + L2_SB);
    float* SAL = (float*)(smem_raw + L2_ALPHA);
    float* SBE = (float*)(smem_raw + L2_BETA);
    float* SWO = (float*)(smem_raw + L2_SWO);

    int t = threadIdx.x;
    int nb = blockIdx.x * 128;
    int lane = t & 31, w = t >> 5;

    // Stage SA [m][k] fp16: k[0,64) = agg2h, k[64,128) = h. Direct uint4 copy.
#pragma unroll
    for (int it = 0; it < 8; it++) {
        int f = t + 256 * it;            // uint4 id [0,2048)
        int m = f >> 4, g = f & 15;
        int n = nb + m; int nc = n < NN ? n : NN - 1;
        uint4 u = (g < 8) ? __ldg((const uint4*)g_agg2h + (nc * 8 + g))
                          : __ldg((const uint4*)g_h + (nc * 8 + (g - 8)));
        *(uint4*)&SA[m * L2_KH + g * 8] = u;
    }
    // Stage SB [k][n] fp16 from fp32 weights (layout already [k][n])
#pragma unroll
    for (int it = 0; it < 8; it++) {
        int f4 = t + 256 * it;           // float4 id [0,2048)
        int k = f4 >> 4, j = f4 & 15;
        float4 wv = (f4 < 1024) ? __ldg((const float4*)W2l + f4)
                                : __ldg((const float4*)W2r + (f4 - 1024));
        __half2 h01 = __floats2half2_rn(wv.x, wv.y);
        __half2 h23 = __floats2half2_rn(wv.z, wv.w);
        uint2 p;
        p.x = *(unsigned int*)&h01;
        p.y = *(unsigned int*)&h23;
        *(uint2*)&SB[k * L2_NH + j * 4] = p;
    }
    if (t < HIDC) {
        float a = g2[t] * rsqrtf(v2[t] + 1e-5f);
        SAL[t] = a;
        SBE[t] = (b2l[t] - m2[t]) * a + bb2[t];
        SWO[t] = Wlin[t];
    }
    __syncthreads();

    // MMA: warp w -> rows [16w, 16w+16)
    int m0 = w * 16;
    float d[8][4];
#pragma unroll
    for (int j = 0; j < 8; j++)
#pragma unroll
        for (int i = 0; i < 4; i++) d[j][i] = 0.f;

    int arow = m0 + (lane & 15);
    int akk  = (lane >> 4) * 8;
    int brow = lane & 15;

#pragma unroll
    for (int s = 0; s < 8; s++) {
        unsigned afr[4];
        unsigned aaddr = (unsigned)__cvta_generic_to_shared(
            &SA[arow * L2_KH + s * 16 + akk]);
        ldsm_x4(afr, aaddr);
#pragma unroll
        for (int j = 0; j < 8; j++) {
            unsigned b0, b1;
            unsigned baddr = (unsigned)__cvta_generic_to_shared(
                &SB[(s * 16 + brow) * L2_NH + j * 8]);
            ldsm_x2t(b0, b1, baddr);
            mma16816(d[j], afr, b0, b1);
        }
    }

    // Epilogue: BN + ReLU + head dot on D fragments.
    int r0 = lane >> 2;
    int cbase = 2 * (lane & 3);
    float p0 = 0.f, p1 = 0.f;
#pragma unroll
    for (int j = 0; j < 8; j++) {
        int c = 8 * j + cbase;
        float A0 = SAL[c],   B0 = SBE[c],   W0 = SWO[c];
        float A1 = SAL[c+1], B1 = SBE[c+1], W1 = SWO[c+1];
        p0 += fmaxf(d[j][0] * A0 + B0, 0.f) * W0
            + fmaxf(d[j][1] * A1 + B1, 0.f) * W1;
        p1 += fmaxf(d[j][2] * A0 + B0, 0.f) * W0
            + fmaxf(d[j][3] * A1 + B1, 0.f) * W1;
    }
    p0 += __shfl_xor_sync(0xFFFFFFFFu, p0, 1);
    p0 += __shfl_xor_sync(0xFFFFFFFFu, p0, 2);
    p1 += __shfl_xor_sync(0xFFFFFFFFu, p1, 1);
    p1 += __shfl_xor_sync(0xFFFFFFFFu, p1, 2);
    if ((lane & 3) == 0) {
        float bb = __ldg(&blin[0]);
        int n1 = nb + m0 + r0;
        int n2 = n1 + 8;
        if (n1 < NN) out[n1] = p0 + bb;
        if (n2 < NN) out[n2] = p1 + bb;
    }
}

// ============================================================================
// Launch — 5 kernels
// ============================================================================
extern "C" void kernel_launch(void* const* d_in, const int* in_sizes, int n_in,
                              void* d_out, int out_size) {
    const float* x   = (const float*)d_in[0];
    const int*   ei  = (const int*)d_in[1];   // int32 (jax x64 disabled)
    const int*   src = ei;
    const int*   dst = ei + EE;
    const float* W1l  = (const float*)d_in[2];
    const float* b1l  = (const float*)d_in[3];
    const float* W1r  = (const float*)d_in[4];
    const float* bn1g = (const float*)d_in[5];
    const float* bn1b = (const float*)d_in[6];
    const float* bn1m = (const float*)d_in[7];
    const float* bn1v = (const float*)d_in[8];
    const float* W2l  = (const float*)d_in[9];
    const float* b2l  = (const float*)d_in[10];
    const float* W2r  = (const float*)d_in[11];
    const float* bn2g = (const float*)d_in[12];
    const float* bn2b = (const float*)d_in[13];
    const float* bn2m = (const float*)d_in[14];
    const float* bn2v = (const float*)d_in[15];
    const float* Wlin = (const float*)d_in[16];
    const float* blin = (const float*)d_in[17];
    float* out = (float*)d_out;

    cudaFuncSetAttribute(k_layer1, cudaFuncAttributeMaxDynamicSharedMemorySize, L1_SMEM);
    cudaFuncSetAttribute(k_layer2, cudaFuncAttributeMaxDynamicSharedMemorySize, L2_SMEM);

    int nblk  = (NN + 127) / 128;              // 391
    int fblk  = (FILL_T + XCVT_T + 255) / 256; // 1563
    int a1blk = (NN * 4 + 255) / 256;          // 782   (8 nodes/warp)
    int a2blk = (NN * 8 + 255) / 256;          // 1563  (4 nodes/warp)

    k_fill<<<fblk, 256>>>(src, dst, x);
    k_agg1<<<a1blk, 256>>>();
    k_layer1<<<nblk, 256, L1_SMEM>>>(W1l, b1l, W1r, bn1g, bn1b, bn1m, bn1v);
    k_agg2<<<a2blk, 256>>>();
    k_layer2<<<nblk, 256, L2_SMEM>>>(W2l, b2l, W2r, bn2g, bn2b, bn2m, bn2v,
                                     Wlin, blin, out);
}